// round 1
// baseline (speedup 1.0000x reference)
#include <cuda_runtime.h>
#include <math.h>

// Shapes (fixed)
#define BB 8
#define SS 14
#define DD 2048
#define CC 20
#define WDIM 300
#define II 1024
#define NPOS 1568      // BB*SS*SS
#define PP 196         // SS*SS

// Scratch (no allocation allowed -> __device__ globals)
__device__ float g_himg[NPOS * II];     // 6.4 MB
__device__ float g_hword[CC * II];
__device__ float g_w34[II];
__device__ float g_b34;
__device__ float g_logits[NPOS * CC];

// ---------------------------------------------------------------------------
// K1: h_word[c,i] = sum_d wordF[c,d] * W2[i,d]
// ---------------------------------------------------------------------------
__global__ void k_hword(const float* __restrict__ wordF, const float* __restrict__ W2) {
    int c = blockIdx.x;
    __shared__ float sw[WDIM];
    for (int d = threadIdx.x; d < WDIM; d += blockDim.x) sw[d] = wordF[c * WDIM + d];
    __syncthreads();
    for (int i = threadIdx.x; i < II; i += blockDim.x) {
        const float* w2r = &W2[i * WDIM];
        float a0 = 0.f, a1 = 0.f, a2 = 0.f, a3 = 0.f;
        #pragma unroll 4
        for (int d = 0; d < WDIM; d += 4) {
            a0 += sw[d + 0] * w2r[d + 0];
            a1 += sw[d + 1] * w2r[d + 1];
            a2 += sw[d + 2] * w2r[d + 2];
            a3 += sw[d + 3] * w2r[d + 3];
        }
        g_hword[c * II + i] = (a0 + a1) + (a2 + a3);
    }
}

// ---------------------------------------------------------------------------
// K2: w34[i] = sum_j W4[j]*W3[j,i];  b34 = W4.b3 + b4
// ---------------------------------------------------------------------------
__global__ void k_w34(const float* __restrict__ W3, const float* __restrict__ W4,
                      const float* __restrict__ b3, const float* __restrict__ b4) {
    int i = blockIdx.x * blockDim.x + threadIdx.x;  // grid 4 x 256
    float acc = 0.f;
    for (int j = 0; j < II; j++) acc += W4[j] * W3[j * II + i];
    g_w34[i] = acc;

    if (blockIdx.x == 0) {
        __shared__ float sred[256];
        float a = 0.f;
        for (int j = threadIdx.x; j < II; j += 256) a += W4[j] * b3[j];
        sred[threadIdx.x] = a;
        __syncthreads();
        for (int s = 128; s > 0; s >>= 1) {
            if (threadIdx.x < s) sred[threadIdx.x] += sred[threadIdx.x + s];
            __syncthreads();
        }
        if (threadIdx.x == 0) g_b34 = sred[0] + b4[0];
    }
}

// ---------------------------------------------------------------------------
// K3: h_img = X @ W1^T   ([1568,2048] x [1024,2048]^T), fp32 FFMA SGEMM
// 64x64 tile, BK=16, 256 threads, 4x4 microtile
// ---------------------------------------------------------------------------
__global__ __launch_bounds__(256) void k_gemm_himg(const float* __restrict__ A,
                                                   const float* __restrict__ Bw) {
    __shared__ float As[16][64];
    __shared__ float Bs[16][64];
    const int bm = blockIdx.y * 64;
    const int bn = blockIdx.x * 64;
    const int tid = threadIdx.x;
    const int tr = tid >> 2;           // 0..63
    const int tc4 = (tid & 3) * 4;     // 0,4,8,12
    const int ty = tid >> 4;           // 0..15
    const int tx = tid & 15;           // 0..15

    float acc[4][4];
    #pragma unroll
    for (int i = 0; i < 4; i++)
        #pragma unroll
        for (int j = 0; j < 4; j++) acc[i][j] = 0.f;

    const int am = bm + tr;
    const bool am_ok = (am < NPOS);
    const int bnr = bn + tr;

    for (int k0 = 0; k0 < DD; k0 += 16) {
        float4 av = am_ok ? *(const float4*)&A[(size_t)am * DD + k0 + tc4]
                          : make_float4(0.f, 0.f, 0.f, 0.f);
        float4 bv = *(const float4*)&Bw[(size_t)bnr * DD + k0 + tc4];
        As[tc4 + 0][tr] = av.x; As[tc4 + 1][tr] = av.y;
        As[tc4 + 2][tr] = av.z; As[tc4 + 3][tr] = av.w;
        Bs[tc4 + 0][tr] = bv.x; Bs[tc4 + 1][tr] = bv.y;
        Bs[tc4 + 2][tr] = bv.z; Bs[tc4 + 3][tr] = bv.w;
        __syncthreads();

        #pragma unroll
        for (int kk = 0; kk < 16; kk++) {
            float4 a = *(const float4*)&As[kk][ty * 4];
            float4 b = *(const float4*)&Bs[kk][tx * 4];
            acc[0][0] += a.x * b.x; acc[0][1] += a.x * b.y; acc[0][2] += a.x * b.z; acc[0][3] += a.x * b.w;
            acc[1][0] += a.y * b.x; acc[1][1] += a.y * b.y; acc[1][2] += a.y * b.z; acc[1][3] += a.y * b.w;
            acc[2][0] += a.z * b.x; acc[2][1] += a.z * b.y; acc[2][2] += a.z * b.z; acc[2][3] += a.z * b.w;
            acc[3][0] += a.w * b.x; acc[3][1] += a.w * b.y; acc[3][2] += a.w * b.z; acc[3][3] += a.w * b.w;
        }
        __syncthreads();
    }

    #pragma unroll
    for (int i = 0; i < 4; i++) {
        int row = bm + ty * 4 + i;
        if (row < NPOS) {
            float4 v = make_float4(acc[i][0], acc[i][1], acc[i][2], acc[i][3]);
            *(float4*)&g_himg[(size_t)row * II + bn + tx * 4] = v;
        }
    }
}

// ---------------------------------------------------------------------------
// K4: logits[n,c] = sum_i tanh(h_img[n,i]*h_word[c,i]) * w34[i] + b34
// 1 block per n, 128 threads, 8 i's per thread
// ---------------------------------------------------------------------------
__global__ __launch_bounds__(128) void k_logits() {
    const int n = blockIdx.x;
    const int tid = threadIdx.x;
    const int i0 = tid * 8;
    const int lane = tid & 31;
    const int warp = tid >> 5;

    float hi[8], wv[8];
    {
        const float4* hp = (const float4*)&g_himg[(size_t)n * II + i0];
        float4 h0 = hp[0], h1 = hp[1];
        hi[0] = h0.x; hi[1] = h0.y; hi[2] = h0.z; hi[3] = h0.w;
        hi[4] = h1.x; hi[5] = h1.y; hi[6] = h1.z; hi[7] = h1.w;
        const float4* wp = (const float4*)&g_w34[i0];
        float4 w0 = wp[0], w1 = wp[1];
        wv[0] = w0.x; wv[1] = w0.y; wv[2] = w0.z; wv[3] = w0.w;
        wv[4] = w1.x; wv[5] = w1.y; wv[6] = w1.z; wv[7] = w1.w;
    }

    __shared__ float red[CC * 4];

    for (int c = 0; c < CC; c++) {
        const float4* hwp = (const float4*)&g_hword[(size_t)c * II + i0];
        float4 w0 = hwp[0], w1 = hwp[1];
        float a = 0.f;
        a += tanhf(hi[0] * w0.x) * wv[0];
        a += tanhf(hi[1] * w0.y) * wv[1];
        a += tanhf(hi[2] * w0.z) * wv[2];
        a += tanhf(hi[3] * w0.w) * wv[3];
        a += tanhf(hi[4] * w1.x) * wv[4];
        a += tanhf(hi[5] * w1.y) * wv[5];
        a += tanhf(hi[6] * w1.z) * wv[6];
        a += tanhf(hi[7] * w1.w) * wv[7];
        // warp reduce
        a += __shfl_down_sync(0xffffffff, a, 16);
        a += __shfl_down_sync(0xffffffff, a, 8);
        a += __shfl_down_sync(0xffffffff, a, 4);
        a += __shfl_down_sync(0xffffffff, a, 2);
        a += __shfl_down_sync(0xffffffff, a, 1);
        if (lane == 0) red[c * 4 + warp] = a;
    }
    __syncthreads();
    if (tid < CC) {
        float l = red[tid * 4] + red[tid * 4 + 1] + red[tid * 4 + 2] + red[tid * 4 + 3] + g_b34;
        g_logits[n * CC + tid] = l;
    }
}

// ---------------------------------------------------------------------------
// K5: softmax over the 196 spatial positions per (b,c); writes coef output
// ---------------------------------------------------------------------------
__global__ void k_softmax(float* __restrict__ out_coef) {
    int t = threadIdx.x;
    if (t >= BB * CC) return;
    int b = t / CC, c = t % CC;
    const float* L = &g_logits[(size_t)b * PP * CC + c];
    float mx = -1e30f;
    for (int p = 0; p < PP; p++) mx = fmaxf(mx, L[p * CC]);
    float s = 0.f;
    for (int p = 0; p < PP; p++) s += expf(L[p * CC] - mx);
    float inv = 1.f / s;
    float* O = &out_coef[(size_t)b * PP * CC + c];
    for (int p = 0; p < PP; p++) O[p * CC] = expf(L[p * CC] - mx) * inv;
}

// ---------------------------------------------------------------------------
// K6: fmwc[b,s1,s2,c,d] = img[b,s1,s2,d] * coef[b,s1,s2,c]   (257 MB store)
// ---------------------------------------------------------------------------
__global__ __launch_bounds__(256) void k_fmwc(const float* __restrict__ img,
                                              const float* __restrict__ coef,
                                              float* __restrict__ out_fmwc) {
    const int n = blockIdx.x;
    const int tid = threadIdx.x;
    __shared__ float4 simg[DD / 4];
    __shared__ float sc[CC];
    const float4* ip = (const float4*)&img[(size_t)n * DD];
    simg[tid] = ip[tid];
    simg[tid + 256] = ip[tid + 256];
    if (tid < CC) sc[tid] = coef[(size_t)n * CC + tid];
    __syncthreads();

    float4* op = (float4*)&out_fmwc[(size_t)n * CC * DD];
    #pragma unroll 4
    for (int idx = tid; idx < CC * (DD / 4); idx += 256) {
        int c = idx >> 9;        // /512
        int d = idx & 511;
        float4 v = simg[d];
        float s = sc[c];
        op[idx] = make_float4(v.x * s, v.y * s, v.z * s, v.w * s);
    }
}

// ---------------------------------------------------------------------------
// K7: semantic[b,c,d] = sum_p coef[b,p,c] * img[b,p,d]
// grid (dchunks=8, b=8), 256 threads, one d per thread
// ---------------------------------------------------------------------------
__global__ __launch_bounds__(256) void k_semantic(const float* __restrict__ img,
                                                  const float* __restrict__ coef,
                                                  float* __restrict__ out_sem) {
    const int b = blockIdx.y;
    const int d = blockIdx.x * 256 + threadIdx.x;
    __shared__ float4 scoef[PP * CC / 4];   // 196*20 floats = 15.7 KB
    const float4* cp = (const float4*)&coef[(size_t)b * PP * CC];
    for (int idx = threadIdx.x; idx < PP * CC / 4; idx += 256) scoef[idx] = cp[idx];
    __syncthreads();

    float acc[CC];
    #pragma unroll
    for (int c = 0; c < CC; c++) acc[c] = 0.f;

    const float* ip = &img[(size_t)b * PP * DD + d];
    #pragma unroll 2
    for (int p = 0; p < PP; p++) {
        float v = ip[(size_t)p * DD];
        #pragma unroll
        for (int c4 = 0; c4 < 5; c4++) {
            float4 cf = scoef[p * 5 + c4];
            acc[c4 * 4 + 0] += cf.x * v;
            acc[c4 * 4 + 1] += cf.y * v;
            acc[c4 * 4 + 2] += cf.z * v;
            acc[c4 * 4 + 3] += cf.w * v;
        }
    }
    #pragma unroll
    for (int c = 0; c < CC; c++)
        out_sem[((size_t)b * CC + c) * DD + d] = acc[c];
}

// ---------------------------------------------------------------------------
extern "C" void kernel_launch(void* const* d_in, const int* in_sizes, int n_in,
                              void* d_out, int out_size) {
    const float* img   = (const float*)d_in[0];  // [8,14,14,2048]
    const float* wordF = (const float*)d_in[1];  // [20,300]
    const float* W1    = (const float*)d_in[2];  // [1024,2048]
    const float* W2    = (const float*)d_in[3];  // [1024,300]
    const float* W3    = (const float*)d_in[4];  // [1024,1024]
    const float* b3    = (const float*)d_in[5];  // [1024]
    const float* W4    = (const float*)d_in[6];  // [1,1024]
    const float* b4    = (const float*)d_in[7];  // [1]

    float* out = (float*)d_out;
    float* out_sem  = out;                                      // 8*20*2048
    float* out_fmwc = out_sem + (size_t)BB * CC * DD;           // 8*14*14*20*2048
    float* out_coef = out_fmwc + (size_t)NPOS * CC * DD;        // 8*14*14*20

    k_hword<<<CC, 256>>>(wordF, W2);
    k_w34<<<II / 256, 256>>>(W3, W4, b3, b4);
    k_gemm_himg<<<dim3(II / 64, (NPOS + 63) / 64), 256>>>(img, W1);
    k_logits<<<NPOS, 128>>>();
    k_softmax<<<1, 256>>>(out_coef);
    k_fmwc<<<NPOS, 256>>>(img, out_coef, out_fmwc);
    k_semantic<<<dim3(DD / 256, BB), 256>>>(img, out_coef, out_sem);
}

// round 3
// speedup vs baseline: 1.3692x; 1.3692x over previous
#include <cuda_runtime.h>
#include <cuda_bf16.h>
#include <math.h>
#include <stdint.h>

// Shapes (fixed)
#define BB 8
#define SS 14
#define DD 2048
#define CC 20
#define WDIM 300
#define II 1024
#define NPOS 1568      // BB*SS*SS
#define PP 196         // SS*SS

#define MTILES 13
#define MPAD (MTILES * 128)   // 1664

// Scratch (no allocation allowed -> __device__ globals)
__device__ float g_himg[NPOS * II];     // 6.4 MB
__device__ float g_hword[CC * II];
__device__ float g_w34[II];
__device__ float g_b34;
__device__ float g_logits[NPOS * CC];
__device__ __align__(256) __nv_bfloat16 g_Ahi[(size_t)MPAD * DD];
__device__ __align__(256) __nv_bfloat16 g_Alo[(size_t)MPAD * DD];
__device__ __align__(256) __nv_bfloat16 g_Bhi[(size_t)II * DD];
__device__ __align__(256) __nv_bfloat16 g_Blo[(size_t)II * DD];

// ---------------------------------------------------------------------------
// PTX helpers (base PTX only: sm_80+ features, compile for plain compute_103)
// ---------------------------------------------------------------------------
__device__ __forceinline__ uint32_t cvta_smem(const void* p) {
    uint32_t a;
    asm("{ .reg .u64 t; cvta.to.shared.u64 t, %1; cvt.u32.u64 %0, t; }"
        : "=r"(a) : "l"(p));
    return a;
}

__device__ __forceinline__ float fast_tanh(float x) {
    float r;
    asm("tanh.approx.f32 %0, %1;" : "=f"(r) : "f"(x));
    return r;
}

__device__ __forceinline__ void cp_async16(uint32_t s, const void* g) {
    asm volatile("cp.async.cg.shared.global [%0], [%1], 16;" :: "r"(s), "l"(g));
}
#define CP_COMMIT() asm volatile("cp.async.commit_group;" ::: "memory")
#define CP_WAIT2()  asm volatile("cp.async.wait_group 2;" ::: "memory")

__device__ __forceinline__ void ldsm_x4(uint32_t* r, uint32_t addr) {
    asm volatile("ldmatrix.sync.aligned.m8n8.x4.shared.b16 {%0,%1,%2,%3}, [%4];"
                 : "=r"(r[0]), "=r"(r[1]), "=r"(r[2]), "=r"(r[3]) : "r"(addr));
}

__device__ __forceinline__ void mma_bf16(float* d, const uint32_t* a, const uint32_t* b) {
    asm volatile(
        "mma.sync.aligned.m16n8k16.row.col.f32.bf16.bf16.f32 "
        "{%0,%1,%2,%3}, {%4,%5,%6,%7}, {%8,%9}, {%0,%1,%2,%3};"
        : "+f"(d[0]), "+f"(d[1]), "+f"(d[2]), "+f"(d[3])
        : "r"(a[0]), "r"(a[1]), "r"(a[2]), "r"(a[3]), "r"(b[0]), "r"(b[1]));
}

// ---------------------------------------------------------------------------
// Conversion kernels: fp32 -> (bf16 hi, bf16 lo)
// ---------------------------------------------------------------------------
__device__ __forceinline__ uint32_t pack_bf2(float a, float b) {
    __nv_bfloat162 h = __floats2bfloat162_rn(a, b);
    return *reinterpret_cast<uint32_t*>(&h);
}

__global__ __launch_bounds__(256) void k_convA(const float* __restrict__ img) {
    size_t t = (size_t)blockIdx.x * 256 + threadIdx.x;
    size_t base = t * 4;                       // element index into [MPAD*DD]
    size_t row = base / DD;
    float4 v = make_float4(0.f, 0.f, 0.f, 0.f);
    if (row < NPOS) v = *(const float4*)&img[base];
    float hx = __bfloat162float(__float2bfloat16(v.x));
    float hy = __bfloat162float(__float2bfloat16(v.y));
    float hz = __bfloat162float(__float2bfloat16(v.z));
    float hw = __bfloat162float(__float2bfloat16(v.w));
    uint2 hi = make_uint2(pack_bf2(hx, hy), pack_bf2(hz, hw));
    uint2 lo = make_uint2(pack_bf2(v.x - hx, v.y - hy), pack_bf2(v.z - hz, v.w - hw));
    *(uint2*)&g_Ahi[base] = hi;
    *(uint2*)&g_Alo[base] = lo;
}

__global__ __launch_bounds__(256) void k_convB(const float* __restrict__ W1) {
    size_t t = (size_t)blockIdx.x * 256 + threadIdx.x;
    size_t base = t * 4;
    float4 v = *(const float4*)&W1[base];
    float hx = __bfloat162float(__float2bfloat16(v.x));
    float hy = __bfloat162float(__float2bfloat16(v.y));
    float hz = __bfloat162float(__float2bfloat16(v.z));
    float hw = __bfloat162float(__float2bfloat16(v.w));
    uint2 hi = make_uint2(pack_bf2(hx, hy), pack_bf2(hz, hw));
    uint2 lo = make_uint2(pack_bf2(v.x - hx, v.y - hy), pack_bf2(v.z - hz, v.w - hw));
    *(uint2*)&g_Bhi[base] = hi;
    *(uint2*)&g_Blo[base] = lo;
}

// ---------------------------------------------------------------------------
// mma.sync GEMM: h_img[M=1568(pad1664), N=1024] = A[M,2048] @ W1[N,2048]^T
// split-bf16 3-MMA. BM=BN=128, BK=16, 3-stage cp.async pipeline (48 KB smem).
// 8 warps: warp_m = wid%4 (32 rows), warp_n = wid/4 (64 cols).
// ---------------------------------------------------------------------------
#define BK 16
#define MAT_BYTES (128 * BK * 2)        // 4096 B per matrix per stage
#define STAGE_BYTES (4 * MAT_BYTES)     // Ahi, Alo, Bhi, Blo = 16 KB
#define NSTAGE 3
#define GEMM_SMEM (NSTAGE * STAGE_BYTES)  // 49152 = 48 KB (no attribute needed)
#define NK (DD / BK)                    // 128

#define AHI_OFF 0
#define ALO_OFF MAT_BYTES
#define BHI_OFF (2 * MAT_BYTES)
#define BLO_OFF (3 * MAT_BYTES)

// swizzled byte offset within one 128x16 bf16 matrix (32B rows, 16B chunks)
__device__ __forceinline__ uint32_t swz(int row, int chunk) {
    return (uint32_t)(row * 32 + ((chunk ^ ((row >> 2) & 1)) * 16));
}

__global__ __launch_bounds__(256) void k_gemm_mma() {
    extern __shared__ __align__(16) char dsm[];
    const uint32_t smem = cvta_smem(dsm);

    const int tid = threadIdx.x;
    const int wid = tid >> 5;
    const int lane = tid & 31;
    const int bm = blockIdx.y * 128;
    const int bn = blockIdx.x * 128;
    const int wm = (wid & 3) * 32;       // warp row offset in tile
    const int wn = (wid >> 2) * 64;      // warp col offset in tile

    // global load mapping: each thread does 1 x 16B per matrix per stage
    const int grow = tid >> 1;           // 0..127
    const int gchunk = tid & 1;          // 0..1
    const __nv_bfloat16* pAhi = &g_Ahi[(size_t)(bm + grow) * DD + gchunk * 8];
    const __nv_bfloat16* pAlo = &g_Alo[(size_t)(bm + grow) * DD + gchunk * 8];
    const __nv_bfloat16* pBhi = &g_Bhi[(size_t)(bn + grow) * DD + gchunk * 8];
    const __nv_bfloat16* pBlo = &g_Blo[(size_t)(bn + grow) * DD + gchunk * 8];
    const uint32_t s_w = swz(grow, gchunk);

    // ldmatrix address offsets (within one matrix region)
    uint32_t aoff[2], boff[4];
    {
        int r = lane & 15, c = lane >> 4;
        aoff[0] = swz(wm + r, c);
        aoff[1] = swz(wm + 16 + r, c);
        int br = wn + ((lane >> 4) * 8) + (lane & 7);
        int bc = (lane >> 3) & 1;
        boff[0] = swz(br, bc);
        boff[1] = swz(br + 16, bc);
        boff[2] = swz(br + 32, bc);
        boff[3] = swz(br + 48, bc);
    }

    float acc[2][8][4];
    #pragma unroll
    for (int i = 0; i < 2; i++)
        #pragma unroll
        for (int j = 0; j < 8; j++)
            #pragma unroll
            for (int q = 0; q < 4; q++) acc[i][j][q] = 0.f;

    auto load_stage = [&](int kc, int buf) {
        uint32_t sb = smem + buf * STAGE_BYTES + s_w;
        size_t go = (size_t)kc * BK;
        cp_async16(sb + AHI_OFF, pAhi + go);
        cp_async16(sb + ALO_OFF, pAlo + go);
        cp_async16(sb + BHI_OFF, pBhi + go);
        cp_async16(sb + BLO_OFF, pBlo + go);
    };

    load_stage(0, 0); CP_COMMIT();
    load_stage(1, 1); CP_COMMIT();

    int buf = 0;
    for (int it = 0; it < NK; it++) {
        if (it + 2 < NK) load_stage(it + 2, (buf + 2) % NSTAGE);
        CP_COMMIT();
        CP_WAIT2();
        __syncthreads();

        uint32_t sb = smem + buf * STAGE_BYTES;
        uint32_t ahi[2][4], alo[2][4], bhi[8][2], blo[8][2];
        #pragma unroll
        for (int m = 0; m < 2; m++) {
            ldsm_x4(ahi[m], sb + AHI_OFF + aoff[m]);
            ldsm_x4(alo[m], sb + ALO_OFF + aoff[m]);
        }
        #pragma unroll
        for (int p = 0; p < 4; p++) {
            uint32_t t4[4];
            ldsm_x4(t4, sb + BHI_OFF + boff[p]);
            bhi[2 * p][0] = t4[0]; bhi[2 * p][1] = t4[1];
            bhi[2 * p + 1][0] = t4[2]; bhi[2 * p + 1][1] = t4[3];
            ldsm_x4(t4, sb + BLO_OFF + boff[p]);
            blo[2 * p][0] = t4[0]; blo[2 * p][1] = t4[1];
            blo[2 * p + 1][0] = t4[2]; blo[2 * p + 1][1] = t4[3];
        }
        #pragma unroll
        for (int m = 0; m < 2; m++)
            #pragma unroll
            for (int n = 0; n < 8; n++) {
                mma_bf16(acc[m][n], ahi[m], bhi[n]);
                mma_bf16(acc[m][n], ahi[m], blo[n]);
                mma_bf16(acc[m][n], alo[m], bhi[n]);
            }
        __syncthreads();
        buf = (buf + 1) % NSTAGE;
    }

    // epilogue: d frag lane mapping: rows l/4 (+8), cols 2*(l%4)+{0,1}
    const int er = lane >> 2;
    const int ec = (lane & 3) * 2;
    #pragma unroll
    for (int m = 0; m < 2; m++) {
        int row0 = bm + wm + m * 16 + er;
        #pragma unroll
        for (int n = 0; n < 8; n++) {
            int col = bn + wn + n * 8 + ec;
            if (row0 < NPOS)
                *(float2*)&g_himg[(size_t)row0 * II + col] = make_float2(acc[m][n][0], acc[m][n][1]);
            if (row0 + 8 < NPOS)
                *(float2*)&g_himg[(size_t)(row0 + 8) * II + col] = make_float2(acc[m][n][2], acc[m][n][3]);
        }
    }
}

// ---------------------------------------------------------------------------
// K1: h_word[c,i] = sum_d wordF[c,d] * W2[i,d]
// ---------------------------------------------------------------------------
__global__ void k_hword(const float* __restrict__ wordF, const float* __restrict__ W2) {
    int c = blockIdx.x;
    __shared__ float sw[WDIM];
    for (int d = threadIdx.x; d < WDIM; d += blockDim.x) sw[d] = wordF[c * WDIM + d];
    __syncthreads();
    for (int i = threadIdx.x; i < II; i += blockDim.x) {
        const float* w2r = &W2[i * WDIM];
        float a0 = 0.f, a1 = 0.f, a2 = 0.f, a3 = 0.f;
        #pragma unroll 4
        for (int d = 0; d < WDIM; d += 4) {
            a0 += sw[d + 0] * w2r[d + 0];
            a1 += sw[d + 1] * w2r[d + 1];
            a2 += sw[d + 2] * w2r[d + 2];
            a3 += sw[d + 3] * w2r[d + 3];
        }
        g_hword[c * II + i] = (a0 + a1) + (a2 + a3);
    }
}

// ---------------------------------------------------------------------------
// K2: w34[i] = sum_j W4[j]*W3[j,i];  b34 = W4.b3 + b4
// ---------------------------------------------------------------------------
__global__ void k_w34(const float* __restrict__ W3, const float* __restrict__ W4,
                      const float* __restrict__ b3, const float* __restrict__ b4) {
    int i = blockIdx.x * blockDim.x + threadIdx.x;  // grid 4 x 256
    float acc = 0.f;
    for (int j = 0; j < II; j++) acc += W4[j] * W3[j * II + i];
    g_w34[i] = acc;

    if (blockIdx.x == 0) {
        __shared__ float sred[256];
        float a = 0.f;
        for (int j = threadIdx.x; j < II; j += 256) a += W4[j] * b3[j];
        sred[threadIdx.x] = a;
        __syncthreads();
        for (int s = 128; s > 0; s >>= 1) {
            if (threadIdx.x < s) sred[threadIdx.x] += sred[threadIdx.x + s];
            __syncthreads();
        }
        if (threadIdx.x == 0) g_b34 = sred[0] + b4[0];
    }
}

// ---------------------------------------------------------------------------
// K4: logits[n,c] = sum_i tanh(h_img[n,i]*h_word[c,i]) * w34[i] + b34
// ---------------------------------------------------------------------------
__global__ __launch_bounds__(128) void k_logits() {
    const int n = blockIdx.x;
    const int tid = threadIdx.x;
    const int i0 = tid * 8;
    const int lane = tid & 31;
    const int warp = tid >> 5;

    float hi[8], wv[8];
    {
        const float4* hp = (const float4*)&g_himg[(size_t)n * II + i0];
        float4 h0 = hp[0], h1 = hp[1];
        hi[0] = h0.x; hi[1] = h0.y; hi[2] = h0.z; hi[3] = h0.w;
        hi[4] = h1.x; hi[5] = h1.y; hi[6] = h1.z; hi[7] = h1.w;
        const float4* wp = (const float4*)&g_w34[i0];
        float4 w0 = wp[0], w1 = wp[1];
        wv[0] = w0.x; wv[1] = w0.y; wv[2] = w0.z; wv[3] = w0.w;
        wv[4] = w1.x; wv[5] = w1.y; wv[6] = w1.z; wv[7] = w1.w;
    }

    __shared__ float red[CC * 4];

    for (int c = 0; c < CC; c++) {
        const float4* hwp = (const float4*)&g_hword[(size_t)c * II + i0];
        float4 w0 = hwp[0], w1 = hwp[1];
        float a = 0.f;
        a += fast_tanh(hi[0] * w0.x) * wv[0];
        a += fast_tanh(hi[1] * w0.y) * wv[1];
        a += fast_tanh(hi[2] * w0.z) * wv[2];
        a += fast_tanh(hi[3] * w0.w) * wv[3];
        a += fast_tanh(hi[4] * w1.x) * wv[4];
        a += fast_tanh(hi[5] * w1.y) * wv[5];
        a += fast_tanh(hi[6] * w1.z) * wv[6];
        a += fast_tanh(hi[7] * w1.w) * wv[7];
        a += __shfl_down_sync(0xffffffff, a, 16);
        a += __shfl_down_sync(0xffffffff, a, 8);
        a += __shfl_down_sync(0xffffffff, a, 4);
        a += __shfl_down_sync(0xffffffff, a, 2);
        a += __shfl_down_sync(0xffffffff, a, 1);
        if (lane == 0) red[c * 4 + warp] = a;
    }
    __syncthreads();
    if (tid < CC) {
        float l = red[tid * 4] + red[tid * 4 + 1] + red[tid * 4 + 2] + red[tid * 4 + 3] + g_b34;
        g_logits[n * CC + tid] = l;
    }
}

// ---------------------------------------------------------------------------
// K5: softmax over the 196 spatial positions per (b,c); writes coef output
// ---------------------------------------------------------------------------
__global__ void k_softmax(float* __restrict__ out_coef) {
    int t = threadIdx.x;
    if (t >= BB * CC) return;
    int b = t / CC, c = t % CC;
    const float* L = &g_logits[(size_t)b * PP * CC + c];
    float mx = -1e30f;
    for (int p = 0; p < PP; p++) mx = fmaxf(mx, L[p * CC]);
    float s = 0.f;
    for (int p = 0; p < PP; p++) s += expf(L[p * CC] - mx);
    float inv = 1.f / s;
    float* O = &out_coef[(size_t)b * PP * CC + c];
    for (int p = 0; p < PP; p++) O[p * CC] = expf(L[p * CC] - mx) * inv;
}

// ---------------------------------------------------------------------------
// K6: fmwc[b,s1,s2,c,d] = img[b,s1,s2,d] * coef[b,s1,s2,c]
// ---------------------------------------------------------------------------
__global__ __launch_bounds__(256) void k_fmwc(const float* __restrict__ img,
                                              const float* __restrict__ coef,
                                              float* __restrict__ out_fmwc) {
    const int n = blockIdx.x;
    const int tid = threadIdx.x;
    __shared__ float4 simg[DD / 4];
    __shared__ float sc[CC];
    const float4* ip = (const float4*)&img[(size_t)n * DD];
    simg[tid] = ip[tid];
    simg[tid + 256] = ip[tid + 256];
    if (tid < CC) sc[tid] = coef[(size_t)n * CC + tid];
    __syncthreads();

    float4* op = (float4*)&out_fmwc[(size_t)n * CC * DD];
    #pragma unroll 4
    for (int idx = tid; idx < CC * (DD / 4); idx += 256) {
        int c = idx >> 9;
        int d = idx & 511;
        float4 v = simg[d];
        float s = sc[c];
        op[idx] = make_float4(v.x * s, v.y * s, v.z * s, v.w * s);
    }
}

// ---------------------------------------------------------------------------
// K7: semantic[b,c,d] = sum_p coef[b,p,c] * img[b,p,d]
// ---------------------------------------------------------------------------
__global__ __launch_bounds__(256) void k_semantic(const float* __restrict__ img,
                                                  const float* __restrict__ coef,
                                                  float* __restrict__ out_sem) {
    const int b = blockIdx.y;
    const int d = blockIdx.x * 256 + threadIdx.x;
    __shared__ float4 scoef[PP * CC / 4];
    const float4* cp = (const float4*)&coef[(size_t)b * PP * CC];
    for (int idx = threadIdx.x; idx < PP * CC / 4; idx += 256) scoef[idx] = cp[idx];
    __syncthreads();

    float acc[CC];
    #pragma unroll
    for (int c = 0; c < CC; c++) acc[c] = 0.f;

    const float* ip = &img[(size_t)b * PP * DD + d];
    #pragma unroll 2
    for (int p = 0; p < PP; p++) {
        float v = ip[(size_t)p * DD];
        #pragma unroll
        for (int c4 = 0; c4 < 5; c4++) {
            float4 cf = scoef[p * 5 + c4];
            acc[c4 * 4 + 0] += cf.x * v;
            acc[c4 * 4 + 1] += cf.y * v;
            acc[c4 * 4 + 2] += cf.z * v;
            acc[c4 * 4 + 3] += cf.w * v;
        }
    }
    #pragma unroll
    for (int c = 0; c < CC; c++)
        out_sem[((size_t)b * CC + c) * DD + d] = acc[c];
}

// ---------------------------------------------------------------------------
extern "C" void kernel_launch(void* const* d_in, const int* in_sizes, int n_in,
                              void* d_out, int out_size) {
    const float* img   = (const float*)d_in[0];  // [8,14,14,2048]
    const float* wordF = (const float*)d_in[1];  // [20,300]
    const float* W1    = (const float*)d_in[2];  // [1024,2048]
    const float* W2    = (const float*)d_in[3];  // [1024,300]
    const float* W3    = (const float*)d_in[4];  // [1024,1024]
    const float* b3    = (const float*)d_in[5];  // [1024]
    const float* W4    = (const float*)d_in[6];  // [1,1024]
    const float* b4    = (const float*)d_in[7];  // [1]

    float* out = (float*)d_out;
    float* out_sem  = out;                                      // 8*20*2048
    float* out_fmwc = out_sem + (size_t)BB * CC * DD;           // 8*14*14*20*2048
    float* out_coef = out_fmwc + (size_t)NPOS * CC * DD;        // 8*14*14*20

    k_convA<<<MPAD * DD / 4 / 256, 256>>>(img);
    k_convB<<<II * DD / 4 / 256, 256>>>(W1);
    k_hword<<<CC, 256>>>(wordF, W2);
    k_w34<<<II / 256, 256>>>(W3, W4, b3, b4);
    k_gemm_mma<<<dim3(II / 128, MTILES), 256, GEMM_SMEM>>>();
    k_logits<<<NPOS, 128>>>();
    k_softmax<<<1, 256>>>(out_coef);
    k_fmwc<<<NPOS, 256>>>(img, out_coef, out_fmwc);
    k_semantic<<<dim3(DD / 256, BB), 256>>>(img, out_coef, out_sem);
}

// round 4
// speedup vs baseline: 2.0223x; 1.4769x over previous
#include <cuda_runtime.h>
#include <cuda_bf16.h>
#include <math.h>
#include <stdint.h>

// Shapes (fixed)
#define BB 8
#define SS 14
#define DD 2048
#define CC 20
#define WDIM 300
#define II 1024
#define NPOS 1568      // BB*SS*SS
#define PP 196         // SS*SS

#define MTILES 13
#define MPAD (MTILES * 128)   // 1664

// Scratch (no allocation allowed -> __device__ globals)
__device__ float g_himg[NPOS * II];     // 6.4 MB
__device__ float g_hword[CC * II];
__device__ float g_w34[II];
__device__ float g_w34p[64 * II];
__device__ float g_b34;
__device__ float g_logits[NPOS * CC];
__device__ __align__(256) __nv_bfloat16 g_Ahi[(size_t)MPAD * DD];
__device__ __align__(256) __nv_bfloat16 g_Alo[(size_t)MPAD * DD];
__device__ __align__(256) __nv_bfloat16 g_Bhi[(size_t)II * DD];
__device__ __align__(256) __nv_bfloat16 g_Blo[(size_t)II * DD];

// ---------------------------------------------------------------------------
// PTX helpers (base PTX only: sm_80+ features, compile for plain compute_103)
// ---------------------------------------------------------------------------
__device__ __forceinline__ uint32_t cvta_smem(const void* p) {
    uint32_t a;
    asm("{ .reg .u64 t; cvta.to.shared.u64 t, %1; cvt.u32.u64 %0, t; }"
        : "=r"(a) : "l"(p));
    return a;
}

__device__ __forceinline__ float fast_tanh(float x) {
    float r;
    asm("tanh.approx.f32 %0, %1;" : "=f"(r) : "f"(x));
    return r;
}

__device__ __forceinline__ void cp_async16(uint32_t s, const void* g) {
    asm volatile("cp.async.cg.shared.global [%0], [%1], 16;" :: "r"(s), "l"(g));
}
#define CP_COMMIT() asm volatile("cp.async.commit_group;" ::: "memory")
#define CP_WAIT1()  asm volatile("cp.async.wait_group 1;" ::: "memory")
#define CP_WAIT0()  asm volatile("cp.async.wait_group 0;" ::: "memory")

__device__ __forceinline__ void ldsm_x4(uint32_t* r, uint32_t addr) {
    asm volatile("ldmatrix.sync.aligned.m8n8.x4.shared.b16 {%0,%1,%2,%3}, [%4];"
                 : "=r"(r[0]), "=r"(r[1]), "=r"(r[2]), "=r"(r[3]) : "r"(addr));
}

__device__ __forceinline__ void mma_bf16(float* d, const uint32_t* a, const uint32_t* b) {
    asm volatile(
        "mma.sync.aligned.m16n8k16.row.col.f32.bf16.bf16.f32 "
        "{%0,%1,%2,%3}, {%4,%5,%6,%7}, {%8,%9}, {%0,%1,%2,%3};"
        : "+f"(d[0]), "+f"(d[1]), "+f"(d[2]), "+f"(d[3])
        : "r"(a[0]), "r"(a[1]), "r"(a[2]), "r"(a[3]), "r"(b[0]), "r"(b[1]));
}

// ---------------------------------------------------------------------------
// Conversion kernels: fp32 -> (bf16 hi, bf16 lo)
// ---------------------------------------------------------------------------
__device__ __forceinline__ uint32_t pack_bf2(float a, float b) {
    __nv_bfloat162 h = __floats2bfloat162_rn(a, b);
    return *reinterpret_cast<uint32_t*>(&h);
}

__global__ __launch_bounds__(256) void k_convA(const float* __restrict__ img) {
    size_t t = (size_t)blockIdx.x * 256 + threadIdx.x;
    size_t base = t * 4;                       // element index into [MPAD*DD]
    size_t row = base / DD;
    float4 v = make_float4(0.f, 0.f, 0.f, 0.f);
    if (row < NPOS) v = *(const float4*)&img[base];
    float hx = __bfloat162float(__float2bfloat16(v.x));
    float hy = __bfloat162float(__float2bfloat16(v.y));
    float hz = __bfloat162float(__float2bfloat16(v.z));
    float hw = __bfloat162float(__float2bfloat16(v.w));
    uint2 hi = make_uint2(pack_bf2(hx, hy), pack_bf2(hz, hw));
    uint2 lo = make_uint2(pack_bf2(v.x - hx, v.y - hy), pack_bf2(v.z - hz, v.w - hw));
    *(uint2*)&g_Ahi[base] = hi;
    *(uint2*)&g_Alo[base] = lo;
}

__global__ __launch_bounds__(256) void k_convB(const float* __restrict__ W1) {
    size_t t = (size_t)blockIdx.x * 256 + threadIdx.x;
    size_t base = t * 4;
    float4 v = *(const float4*)&W1[base];
    float hx = __bfloat162float(__float2bfloat16(v.x));
    float hy = __bfloat162float(__float2bfloat16(v.y));
    float hz = __bfloat162float(__float2bfloat16(v.z));
    float hw = __bfloat162float(__float2bfloat16(v.w));
    uint2 hi = make_uint2(pack_bf2(hx, hy), pack_bf2(hz, hw));
    uint2 lo = make_uint2(pack_bf2(v.x - hx, v.y - hy), pack_bf2(v.z - hz, v.w - hw));
    *(uint2*)&g_Bhi[base] = hi;
    *(uint2*)&g_Blo[base] = lo;
}

// ---------------------------------------------------------------------------
// mma.sync GEMM: h_img[M=1568(pad1664), N=1024] = A[M,2048] @ W1[N,2048]^T
// split-bf16 3-MMA. BM=BN=128, BK=16, 3-stage cp.async pipeline (48 KB smem).
// One __syncthreads per K-iter.
// ---------------------------------------------------------------------------
#define BK 16
#define MAT_BYTES (128 * BK * 2)        // 4096 B per matrix per stage
#define STAGE_BYTES (4 * MAT_BYTES)     // Ahi, Alo, Bhi, Blo = 16 KB
#define NSTAGE 3
#define GEMM_SMEM (NSTAGE * STAGE_BYTES)  // 48 KB
#define NK (DD / BK)                    // 128

#define AHI_OFF 0
#define ALO_OFF MAT_BYTES
#define BHI_OFF (2 * MAT_BYTES)
#define BLO_OFF (3 * MAT_BYTES)

// swizzled byte offset within one 128x16 bf16 matrix (32B rows, 16B chunks)
__device__ __forceinline__ uint32_t swz(int row, int chunk) {
    return (uint32_t)(row * 32 + ((chunk ^ ((row >> 2) & 1)) * 16));
}

__global__ __launch_bounds__(256) void k_gemm_mma() {
    extern __shared__ __align__(16) char dsm[];
    const uint32_t smem = cvta_smem(dsm);

    const int tid = threadIdx.x;
    const int wid = tid >> 5;
    const int lane = tid & 31;
    const int bm = blockIdx.y * 128;
    const int bn = blockIdx.x * 128;
    const int wm = (wid & 3) * 32;       // warp row offset in tile
    const int wn = (wid >> 2) * 64;      // warp col offset in tile

    // global load mapping: each thread does 1 x 16B per matrix per stage
    const int grow = tid >> 1;           // 0..127
    const int gchunk = tid & 1;          // 0..1
    const __nv_bfloat16* pAhi = &g_Ahi[(size_t)(bm + grow) * DD + gchunk * 8];
    const __nv_bfloat16* pAlo = &g_Alo[(size_t)(bm + grow) * DD + gchunk * 8];
    const __nv_bfloat16* pBhi = &g_Bhi[(size_t)(bn + grow) * DD + gchunk * 8];
    const __nv_bfloat16* pBlo = &g_Blo[(size_t)(bn + grow) * DD + gchunk * 8];
    const uint32_t s_w = swz(grow, gchunk);

    // ldmatrix address offsets (within one matrix region)
    uint32_t aoff[2], boff[4];
    {
        int r = lane & 15, c = lane >> 4;
        aoff[0] = swz(wm + r, c);
        aoff[1] = swz(wm + 16 + r, c);
        int br = wn + ((lane >> 4) * 8) + (lane & 7);
        int bc = (lane >> 3) & 1;
        boff[0] = swz(br, bc);
        boff[1] = swz(br + 16, bc);
        boff[2] = swz(br + 32, bc);
        boff[3] = swz(br + 48, bc);
    }

    float acc[2][8][4];
    #pragma unroll
    for (int i = 0; i < 2; i++)
        #pragma unroll
        for (int j = 0; j < 8; j++)
            #pragma unroll
            for (int q = 0; q < 4; q++) acc[i][j][q] = 0.f;

    auto load_stage = [&](int kc, int buf) {
        uint32_t sb = smem + buf * STAGE_BYTES + s_w;
        size_t go = (size_t)kc * BK;
        cp_async16(sb + AHI_OFF, pAhi + go);
        cp_async16(sb + ALO_OFF, pAlo + go);
        cp_async16(sb + BHI_OFF, pBhi + go);
        cp_async16(sb + BLO_OFF, pBlo + go);
    };

    load_stage(0, 0); CP_COMMIT();
    load_stage(1, 1); CP_COMMIT();

    int buf = 0;
    for (int it = 0; it < NK; it++) {
        if (it + 1 < NK) { CP_WAIT1(); } else { CP_WAIT0(); }
        __syncthreads();
        if (it + 2 < NK) { load_stage(it + 2, (buf + 2) % NSTAGE); CP_COMMIT(); }

        uint32_t sb = smem + buf * STAGE_BYTES;
        uint32_t ahi[2][4], alo[2][4], bhi[8][2], blo[8][2];
        #pragma unroll
        for (int m = 0; m < 2; m++) {
            ldsm_x4(ahi[m], sb + AHI_OFF + aoff[m]);
            ldsm_x4(alo[m], sb + ALO_OFF + aoff[m]);
        }
        #pragma unroll
        for (int p = 0; p < 4; p++) {
            uint32_t t4[4];
            ldsm_x4(t4, sb + BHI_OFF + boff[p]);
            bhi[2 * p][0] = t4[0]; bhi[2 * p][1] = t4[1];
            bhi[2 * p + 1][0] = t4[2]; bhi[2 * p + 1][1] = t4[3];
            ldsm_x4(t4, sb + BLO_OFF + boff[p]);
            blo[2 * p][0] = t4[0]; blo[2 * p][1] = t4[1];
            blo[2 * p + 1][0] = t4[2]; blo[2 * p + 1][1] = t4[3];
        }
        #pragma unroll
        for (int m = 0; m < 2; m++)
            #pragma unroll
            for (int n = 0; n < 8; n++) {
                mma_bf16(acc[m][n], ahi[m], bhi[n]);
                mma_bf16(acc[m][n], ahi[m], blo[n]);
                mma_bf16(acc[m][n], alo[m], bhi[n]);
            }
        buf = (buf + 1) % NSTAGE;
    }

    // epilogue: d frag lane mapping: rows l/4 (+8), cols 2*(l%4)+{0,1}
    const int er = lane >> 2;
    const int ec = (lane & 3) * 2;
    #pragma unroll
    for (int m = 0; m < 2; m++) {
        int row0 = bm + wm + m * 16 + er;
        #pragma unroll
        for (int n = 0; n < 8; n++) {
            int col = bn + wn + n * 8 + ec;
            if (row0 < NPOS)
                *(float2*)&g_himg[(size_t)row0 * II + col] = make_float2(acc[m][n][0], acc[m][n][1]);
            if (row0 + 8 < NPOS)
                *(float2*)&g_himg[(size_t)(row0 + 8) * II + col] = make_float2(acc[m][n][2], acc[m][n][3]);
        }
    }
}

// ---------------------------------------------------------------------------
// K1: h_word[c,i] = sum_d wordF[c,d] * W2[i,d]   grid (4, CC)
// ---------------------------------------------------------------------------
__global__ __launch_bounds__(256) void k_hword(const float* __restrict__ wordF,
                                               const float* __restrict__ W2) {
    const int c = blockIdx.y;
    const int i = blockIdx.x * 256 + threadIdx.x;
    __shared__ float sw[WDIM + 4];
    for (int d = threadIdx.x; d < WDIM; d += 256) sw[d] = wordF[c * WDIM + d];
    if (threadIdx.x < 4) sw[WDIM + threadIdx.x] = 0.f;
    __syncthreads();
    const float* w2r = &W2[(size_t)i * WDIM];
    float a0 = 0.f, a1 = 0.f, a2 = 0.f, a3 = 0.f;
    #pragma unroll 5
    for (int d = 0; d < WDIM; d += 4) {
        a0 += sw[d + 0] * w2r[d + 0];
        a1 += sw[d + 1] * w2r[d + 1];
        a2 += sw[d + 2] * w2r[d + 2];
        a3 += sw[d + 3] * w2r[d + 3];
    }
    g_hword[c * II + i] = (a0 + a1) + (a2 + a3);
}

// ---------------------------------------------------------------------------
// K2a: partial w34: block b handles j in [16b, 16b+16); coalesced float4 reads
// ---------------------------------------------------------------------------
__global__ __launch_bounds__(256) void k_w34_part(const float* __restrict__ W3,
                                                  const float* __restrict__ W4) {
    const int b = blockIdx.x;          // 0..63
    const int i4 = threadIdx.x * 4;
    const int j0 = b * 16;
    float4 acc = make_float4(0.f, 0.f, 0.f, 0.f);
    #pragma unroll 4
    for (int j = 0; j < 16; j++) {
        float wj = W4[j0 + j];
        float4 v = *(const float4*)&W3[(size_t)(j0 + j) * II + i4];
        acc.x += wj * v.x; acc.y += wj * v.y; acc.z += wj * v.z; acc.w += wj * v.w;
    }
    *(float4*)&g_w34p[(size_t)b * II + i4] = acc;
}

// K2b: reduce partials + b34
__global__ __launch_bounds__(256) void k_w34_red(const float* __restrict__ b3,
                                                 const float* __restrict__ W4,
                                                 const float* __restrict__ b4) {
    const int i = blockIdx.x * 256 + threadIdx.x;
    float s = 0.f;
    #pragma unroll 8
    for (int k = 0; k < 64; k++) s += g_w34p[(size_t)k * II + i];
    g_w34[i] = s;

    if (blockIdx.x == 0) {
        __shared__ float sred[256];
        float a = 0.f;
        for (int j = threadIdx.x; j < II; j += 256) a += W4[j] * b3[j];
        sred[threadIdx.x] = a;
        __syncthreads();
        for (int st = 128; st > 0; st >>= 1) {
            if (threadIdx.x < st) sred[threadIdx.x] += sred[threadIdx.x + st];
            __syncthreads();
        }
        if (threadIdx.x == 0) g_b34 = sred[0] + b4[0];
    }
}

// ---------------------------------------------------------------------------
// K4: logits[n,c] = sum_i tanh(h_img[n,i]*h_word[c,i]) * w34[i] + b34
// ---------------------------------------------------------------------------
__global__ __launch_bounds__(128) void k_logits() {
    const int n = blockIdx.x;
    const int tid = threadIdx.x;
    const int i0 = tid * 8;
    const int lane = tid & 31;
    const int warp = tid >> 5;

    float hi[8], wv[8];
    {
        const float4* hp = (const float4*)&g_himg[(size_t)n * II + i0];
        float4 h0 = hp[0], h1 = hp[1];
        hi[0] = h0.x; hi[1] = h0.y; hi[2] = h0.z; hi[3] = h0.w;
        hi[4] = h1.x; hi[5] = h1.y; hi[6] = h1.z; hi[7] = h1.w;
        const float4* wp = (const float4*)&g_w34[i0];
        float4 w0 = wp[0], w1 = wp[1];
        wv[0] = w0.x; wv[1] = w0.y; wv[2] = w0.z; wv[3] = w0.w;
        wv[4] = w1.x; wv[5] = w1.y; wv[6] = w1.z; wv[7] = w1.w;
    }

    __shared__ float red[CC * 4];

    for (int c = 0; c < CC; c++) {
        const float4* hwp = (const float4*)&g_hword[(size_t)c * II + i0];
        float4 w0 = hwp[0], w1 = hwp[1];
        float a = 0.f;
        a += fast_tanh(hi[0] * w0.x) * wv[0];
        a += fast_tanh(hi[1] * w0.y) * wv[1];
        a += fast_tanh(hi[2] * w0.z) * wv[2];
        a += fast_tanh(hi[3] * w0.w) * wv[3];
        a += fast_tanh(hi[4] * w1.x) * wv[4];
        a += fast_tanh(hi[5] * w1.y) * wv[5];
        a += fast_tanh(hi[6] * w1.z) * wv[6];
        a += fast_tanh(hi[7] * w1.w) * wv[7];
        a += __shfl_down_sync(0xffffffff, a, 16);
        a += __shfl_down_sync(0xffffffff, a, 8);
        a += __shfl_down_sync(0xffffffff, a, 4);
        a += __shfl_down_sync(0xffffffff, a, 2);
        a += __shfl_down_sync(0xffffffff, a, 1);
        if (lane == 0) red[c * 4 + warp] = a;
    }
    __syncthreads();
    if (tid < CC) {
        float l = red[tid * 4] + red[tid * 4 + 1] + red[tid * 4 + 2] + red[tid * 4 + 3] + g_b34;
        g_logits[n * CC + tid] = l;
    }
}

// ---------------------------------------------------------------------------
// K5: softmax over 196 spatial positions per (b,c); one block per (b,c)
// ---------------------------------------------------------------------------
__global__ __launch_bounds__(256) void k_softmax(float* __restrict__ out_coef) {
    const int b = blockIdx.x / CC;
    const int c = blockIdx.x % CC;
    const int tid = threadIdx.x;
    const int lane = tid & 31;
    const int warp = tid >> 5;
    __shared__ float sm[8];

    float v = -1e30f;
    if (tid < PP) v = g_logits[((size_t)b * PP + tid) * CC + c];

    // block max
    float m = v;
    m = fmaxf(m, __shfl_xor_sync(0xffffffff, m, 16));
    m = fmaxf(m, __shfl_xor_sync(0xffffffff, m, 8));
    m = fmaxf(m, __shfl_xor_sync(0xffffffff, m, 4));
    m = fmaxf(m, __shfl_xor_sync(0xffffffff, m, 2));
    m = fmaxf(m, __shfl_xor_sync(0xffffffff, m, 1));
    if (lane == 0) sm[warp] = m;
    __syncthreads();
    if (warp == 0) {
        float t = sm[lane & 7];
        t = fmaxf(t, __shfl_xor_sync(0xffffffff, t, 4));
        t = fmaxf(t, __shfl_xor_sync(0xffffffff, t, 2));
        t = fmaxf(t, __shfl_xor_sync(0xffffffff, t, 1));
        if (lane == 0) sm[0] = t;
    }
    __syncthreads();
    const float mx = sm[0];
    __syncthreads();

    float e = (tid < PP) ? expf(v - mx) : 0.f;
    float s = e;
    s += __shfl_xor_sync(0xffffffff, s, 16);
    s += __shfl_xor_sync(0xffffffff, s, 8);
    s += __shfl_xor_sync(0xffffffff, s, 4);
    s += __shfl_xor_sync(0xffffffff, s, 2);
    s += __shfl_xor_sync(0xffffffff, s, 1);
    if (lane == 0) sm[warp] = s;
    __syncthreads();
    if (warp == 0) {
        float t = sm[lane & 7];
        t += __shfl_xor_sync(0xffffffff, t, 4);
        t += __shfl_xor_sync(0xffffffff, t, 2);
        t += __shfl_xor_sync(0xffffffff, t, 1);
        if (lane == 0) sm[0] = t;
    }
    __syncthreads();
    const float inv = 1.f / sm[0];

    if (tid < PP) out_coef[((size_t)b * PP + tid) * CC + c] = e * inv;
}

// ---------------------------------------------------------------------------
// K6: fmwc[b,s1,s2,c,d] = img[b,s1,s2,d] * coef[b,s1,s2,c]
// ---------------------------------------------------------------------------
__global__ __launch_bounds__(256) void k_fmwc(const float* __restrict__ img,
                                              const float* __restrict__ coef,
                                              float* __restrict__ out_fmwc) {
    const int n = blockIdx.x;
    const int tid = threadIdx.x;
    __shared__ float4 simg[DD / 4];
    __shared__ float sc[CC];
    const float4* ip = (const float4*)&img[(size_t)n * DD];
    simg[tid] = ip[tid];
    simg[tid + 256] = ip[tid + 256];
    if (tid < CC) sc[tid] = coef[(size_t)n * CC + tid];
    __syncthreads();

    float4* op = (float4*)&out_fmwc[(size_t)n * CC * DD];
    #pragma unroll 4
    for (int idx = tid; idx < CC * (DD / 4); idx += 256) {
        int c = idx >> 9;
        int d = idx & 511;
        float4 v = simg[d];
        float s = sc[c];
        op[idx] = make_float4(v.x * s, v.y * s, v.z * s, v.w * s);
    }
}

// ---------------------------------------------------------------------------
// K7: semantic[b,c,d] = sum_p coef[b,p,c] * img[b,p,d]
// ---------------------------------------------------------------------------
__global__ __launch_bounds__(256) void k_semantic(const float* __restrict__ img,
                                                  const float* __restrict__ coef,
                                                  float* __restrict__ out_sem) {
    const int b = blockIdx.y;
    const int d = blockIdx.x * 256 + threadIdx.x;
    __shared__ float4 scoef[PP * CC / 4];
    const float4* cp = (const float4*)&coef[(size_t)b * PP * CC];
    for (int idx = threadIdx.x; idx < PP * CC / 4; idx += 256) scoef[idx] = cp[idx];
    __syncthreads();

    float acc[CC];
    #pragma unroll
    for (int c = 0; c < CC; c++) acc[c] = 0.f;

    const float* ip = &img[(size_t)b * PP * DD + d];
    #pragma unroll 2
    for (int p = 0; p < PP; p++) {
        float v = ip[(size_t)p * DD];
        #pragma unroll
        for (int c4 = 0; c4 < 5; c4++) {
            float4 cf = scoef[p * 5 + c4];
            acc[c4 * 4 + 0] += cf.x * v;
            acc[c4 * 4 + 1] += cf.y * v;
            acc[c4 * 4 + 2] += cf.z * v;
            acc[c4 * 4 + 3] += cf.w * v;
        }
    }
    #pragma unroll
    for (int c = 0; c < CC; c++)
        out_sem[((size_t)b * CC + c) * DD + d] = acc[c];
}

// ---------------------------------------------------------------------------
extern "C" void kernel_launch(void* const* d_in, const int* in_sizes, int n_in,
                              void* d_out, int out_size) {
    const float* img   = (const float*)d_in[0];  // [8,14,14,2048]
    const float* wordF = (const float*)d_in[1];  // [20,300]
    const float* W1    = (const float*)d_in[2];  // [1024,2048]
    const float* W2    = (const float*)d_in[3];  // [1024,300]
    const float* W3    = (const float*)d_in[4];  // [1024,1024]
    const float* b3    = (const float*)d_in[5];  // [1024]
    const float* W4    = (const float*)d_in[6];  // [1,1024]
    const float* b4    = (const float*)d_in[7];  // [1]

    float* out = (float*)d_out;
    float* out_sem  = out;                                      // 8*20*2048
    float* out_fmwc = out_sem + (size_t)BB * CC * DD;           // 8*14*14*20*2048
    float* out_coef = out_fmwc + (size_t)NPOS * CC * DD;        // 8*14*14*20

    k_convA<<<MPAD * DD / 4 / 256, 256>>>(img);
    k_convB<<<II * DD / 4 / 256, 256>>>(W1);
    k_hword<<<dim3(4, CC), 256>>>(wordF, W2);
    k_w34_part<<<64, 256>>>(W3, W4);
    k_w34_red<<<4, 256>>>(b3, W4, b4);
    k_gemm_mma<<<dim3(II / 128, MTILES), 256, GEMM_SMEM>>>();
    k_logits<<<NPOS, 128>>>();
    k_softmax<<<BB * CC, 256>>>(out_coef);
    k_fmwc<<<NPOS, 256>>>(img, out_coef, out_fmwc);
    k_semantic<<<dim3(DD / 256, BB), 256>>>(img, out_coef, out_sem);
}

// round 5
// speedup vs baseline: 2.6354x; 1.3032x over previous
#include <cuda_runtime.h>
#include <cuda_fp16.h>
#include <math.h>
#include <stdint.h>

// Shapes (fixed)
#define BB 8
#define SS 14
#define DD 2048
#define CC 20
#define WDIM 300
#define II 1024
#define NPOS 1568      // BB*SS*SS
#define PP 196         // SS*SS

#define MTILES 13
#define MPAD (MTILES * 128)   // 1664

// Scratch (no allocation allowed -> __device__ globals)
__device__ float g_himg[NPOS * II];     // 6.4 MB
__device__ float g_hword[CC * II];
__device__ float g_w34[II];
__device__ float g_w34p[64 * II];
__device__ float g_b34;
__device__ float g_logits[NPOS * CC];
__device__ __align__(256) __half g_Ah[(size_t)MPAD * DD];
__device__ __align__(256) __half g_Bh[(size_t)II * DD];

// ---------------------------------------------------------------------------
// PTX helpers (base PTX only)
// ---------------------------------------------------------------------------
__device__ __forceinline__ uint32_t cvta_smem(const void* p) {
    uint32_t a;
    asm("{ .reg .u64 t; cvta.to.shared.u64 t, %1; cvt.u32.u64 %0, t; }"
        : "=r"(a) : "l"(p));
    return a;
}

__device__ __forceinline__ float fast_tanh(float x) {
    float r;
    asm("tanh.approx.f32 %0, %1;" : "=f"(r) : "f"(x));
    return r;
}

__device__ __forceinline__ void cp_async16(uint32_t s, const void* g) {
    asm volatile("cp.async.cg.shared.global [%0], [%1], 16;" :: "r"(s), "l"(g));
}
#define CP_COMMIT() asm volatile("cp.async.commit_group;" ::: "memory")
#define CP_WAIT2()  asm volatile("cp.async.wait_group 2;" ::: "memory")
#define CP_WAIT1()  asm volatile("cp.async.wait_group 1;" ::: "memory")
#define CP_WAIT0()  asm volatile("cp.async.wait_group 0;" ::: "memory")

__device__ __forceinline__ void ldsm_x4(uint32_t* r, uint32_t addr) {
    asm volatile("ldmatrix.sync.aligned.m8n8.x4.shared.b16 {%0,%1,%2,%3}, [%4];"
                 : "=r"(r[0]), "=r"(r[1]), "=r"(r[2]), "=r"(r[3]) : "r"(addr));
}

__device__ __forceinline__ void mma_fp16(float* d, const uint32_t* a, const uint32_t* b) {
    asm volatile(
        "mma.sync.aligned.m16n8k16.row.col.f32.f16.f16.f32 "
        "{%0,%1,%2,%3}, {%4,%5,%6,%7}, {%8,%9}, {%0,%1,%2,%3};"
        : "+f"(d[0]), "+f"(d[1]), "+f"(d[2]), "+f"(d[3])
        : "r"(a[0]), "r"(a[1]), "r"(a[2]), "r"(a[3]), "r"(b[0]), "r"(b[1]));
}

// ---------------------------------------------------------------------------
// Conversion kernels: fp32 -> fp16
// ---------------------------------------------------------------------------
__global__ __launch_bounds__(256) void k_convA(const float* __restrict__ img) {
    size_t t = (size_t)blockIdx.x * 256 + threadIdx.x;
    size_t base = t * 4;                       // element index into [MPAD*DD]
    size_t row = base / DD;
    float4 v = make_float4(0.f, 0.f, 0.f, 0.f);
    if (row < NPOS) v = *(const float4*)&img[base];
    __half2 h0 = __floats2half2_rn(v.x, v.y);
    __half2 h1 = __floats2half2_rn(v.z, v.w);
    uint2 o;
    o.x = *reinterpret_cast<uint32_t*>(&h0);
    o.y = *reinterpret_cast<uint32_t*>(&h1);
    *(uint2*)&g_Ah[base] = o;
}

__global__ __launch_bounds__(256) void k_convB(const float* __restrict__ W1) {
    size_t t = (size_t)blockIdx.x * 256 + threadIdx.x;
    size_t base = t * 4;
    float4 v = *(const float4*)&W1[base];
    __half2 h0 = __floats2half2_rn(v.x, v.y);
    __half2 h1 = __floats2half2_rn(v.z, v.w);
    uint2 o;
    o.x = *reinterpret_cast<uint32_t*>(&h0);
    o.y = *reinterpret_cast<uint32_t*>(&h1);
    *(uint2*)&g_Bh[base] = o;
}

// ---------------------------------------------------------------------------
// mma.sync fp16 GEMM: h_img[1568(pad1664), 1024] = A[M,2048] @ W1[1024,2048]^T
// single pass fp16, fp32 accum. BM=BN=128, BK=16, 4-stage cp.async (32 KB).
// ---------------------------------------------------------------------------
#define BK 16
#define MAT_BYTES (128 * BK * 2)        // 4096 B per matrix per stage
#define STAGE_BYTES (2 * MAT_BYTES)     // A, B = 8 KB
#define NSTAGE 4
#define GEMM_SMEM (NSTAGE * STAGE_BYTES)  // 32 KB
#define NK (DD / BK)                    // 128

#define A_OFF 0
#define B_OFF MAT_BYTES

// swizzled byte offset within one 128x16 fp16 matrix (32B rows, 16B chunks)
__device__ __forceinline__ uint32_t swz(int row, int chunk) {
    return (uint32_t)(row * 32 + ((chunk ^ ((row >> 2) & 1)) * 16));
}

__global__ __launch_bounds__(256) void k_gemm_mma() {
    extern __shared__ __align__(16) char dsm[];
    const uint32_t smem = cvta_smem(dsm);

    const int tid = threadIdx.x;
    const int wid = tid >> 5;
    const int lane = tid & 31;
    const int bm = blockIdx.y * 128;
    const int bn = blockIdx.x * 128;
    const int wm = (wid & 3) * 32;       // warp row offset in tile
    const int wn = (wid >> 2) * 64;      // warp col offset in tile

    // global load mapping: each thread does 1 x 16B per matrix per stage
    const int grow = tid >> 1;           // 0..127
    const int gchunk = tid & 1;          // 0..1
    const __half* pA = &g_Ah[(size_t)(bm + grow) * DD + gchunk * 8];
    const __half* pB = &g_Bh[(size_t)(bn + grow) * DD + gchunk * 8];
    const uint32_t s_w = swz(grow, gchunk);

    // ldmatrix address offsets (within one matrix region)
    uint32_t aoff[2], boff[4];
    {
        int r = lane & 15, c = lane >> 4;
        aoff[0] = swz(wm + r, c);
        aoff[1] = swz(wm + 16 + r, c);
        int br = wn + ((lane >> 4) * 8) + (lane & 7);
        int bc = (lane >> 3) & 1;
        boff[0] = swz(br, bc);
        boff[1] = swz(br + 16, bc);
        boff[2] = swz(br + 32, bc);
        boff[3] = swz(br + 48, bc);
    }

    float acc[2][8][4];
    #pragma unroll
    for (int i = 0; i < 2; i++)
        #pragma unroll
        for (int j = 0; j < 8; j++)
            #pragma unroll
            for (int q = 0; q < 4; q++) acc[i][j][q] = 0.f;

    auto load_stage = [&](int kc, int buf) {
        uint32_t sb = smem + buf * STAGE_BYTES + s_w;
        size_t go = (size_t)kc * BK;
        cp_async16(sb + A_OFF, pA + go);
        cp_async16(sb + B_OFF, pB + go);
    };

    load_stage(0, 0); CP_COMMIT();
    load_stage(1, 1); CP_COMMIT();
    load_stage(2, 2); CP_COMMIT();

    int buf = 0;
    for (int it = 0; it < NK; it++) {
        const int remaining = NK - 1 - it;
        if (remaining >= 2) { CP_WAIT2(); }
        else if (remaining == 1) { CP_WAIT1(); }
        else { CP_WAIT0(); }
        __syncthreads();
        if (it + 3 < NK) { load_stage(it + 3, (buf + 3) & 3); CP_COMMIT(); }

        uint32_t sb = smem + buf * STAGE_BYTES;
        uint32_t af[2][4], bf[8][2];
        #pragma unroll
        for (int m = 0; m < 2; m++) ldsm_x4(af[m], sb + A_OFF + aoff[m]);
        #pragma unroll
        for (int p = 0; p < 4; p++) {
            uint32_t t4[4];
            ldsm_x4(t4, sb + B_OFF + boff[p]);
            bf[2 * p][0] = t4[0]; bf[2 * p][1] = t4[1];
            bf[2 * p + 1][0] = t4[2]; bf[2 * p + 1][1] = t4[3];
        }
        #pragma unroll
        for (int m = 0; m < 2; m++)
            #pragma unroll
            for (int n = 0; n < 8; n++)
                mma_fp16(acc[m][n], af[m], bf[n]);
        buf = (buf + 1) & 3;
    }

    // epilogue: d frag lane mapping: rows l/4 (+8), cols 2*(l%4)+{0,1}
    const int er = lane >> 2;
    const int ec = (lane & 3) * 2;
    #pragma unroll
    for (int m = 0; m < 2; m++) {
        int row0 = bm + wm + m * 16 + er;
        #pragma unroll
        for (int n = 0; n < 8; n++) {
            int col = bn + wn + n * 8 + ec;
            if (row0 < NPOS)
                *(float2*)&g_himg[(size_t)row0 * II + col] = make_float2(acc[m][n][0], acc[m][n][1]);
            if (row0 + 8 < NPOS)
                *(float2*)&g_himg[(size_t)(row0 + 8) * II + col] = make_float2(acc[m][n][2], acc[m][n][3]);
        }
    }
}

// ---------------------------------------------------------------------------
// K1: h_word[c,i] = sum_d wordF[c,d] * W2[i,d]   grid (4, CC)
// ---------------------------------------------------------------------------
__global__ __launch_bounds__(256) void k_hword(const float* __restrict__ wordF,
                                               const float* __restrict__ W2) {
    const int c = blockIdx.y;
    const int i = blockIdx.x * 256 + threadIdx.x;
    __shared__ float sw[WDIM + 4];
    for (int d = threadIdx.x; d < WDIM; d += 256) sw[d] = wordF[c * WDIM + d];
    if (threadIdx.x < 4) sw[WDIM + threadIdx.x] = 0.f;
    __syncthreads();
    const float* w2r = &W2[(size_t)i * WDIM];
    float a0 = 0.f, a1 = 0.f, a2 = 0.f, a3 = 0.f;
    #pragma unroll 5
    for (int d = 0; d < WDIM; d += 4) {
        a0 += sw[d + 0] * w2r[d + 0];
        a1 += sw[d + 1] * w2r[d + 1];
        a2 += sw[d + 2] * w2r[d + 2];
        a3 += sw[d + 3] * w2r[d + 3];
    }
    g_hword[c * II + i] = (a0 + a1) + (a2 + a3);
}

// ---------------------------------------------------------------------------
// K2a: partial w34. grid (4 i-chunks, 64 j-chunks); one i per thread.
// ---------------------------------------------------------------------------
__global__ __launch_bounds__(256) void k_w34_part(const float* __restrict__ W3,
                                                  const float* __restrict__ W4) {
    const int i = blockIdx.x * 256 + threadIdx.x;   // 0..1023
    const int jb = blockIdx.y;                      // 0..63
    const int j0 = jb * 16;
    float acc = 0.f;
    #pragma unroll
    for (int j = 0; j < 16; j++)
        acc += W4[j0 + j] * W3[(size_t)(j0 + j) * II + i];
    g_w34p[(size_t)jb * II + i] = acc;
}

// K2b: reduce partials + b34
__global__ __launch_bounds__(256) void k_w34_red(const float* __restrict__ b3,
                                                 const float* __restrict__ W4,
                                                 const float* __restrict__ b4) {
    const int i = blockIdx.x * 256 + threadIdx.x;
    float s = 0.f;
    #pragma unroll 8
    for (int k = 0; k < 64; k++) s += g_w34p[(size_t)k * II + i];
    g_w34[i] = s;

    if (blockIdx.x == 0) {
        __shared__ float sred[256];
        float a = 0.f;
        for (int j = threadIdx.x; j < II; j += 256) a += W4[j] * b3[j];
        sred[threadIdx.x] = a;
        __syncthreads();
        for (int st = 128; st > 0; st >>= 1) {
            if (threadIdx.x < st) sred[threadIdx.x] += sred[threadIdx.x + st];
            __syncthreads();
        }
        if (threadIdx.x == 0) g_b34 = sred[0] + b4[0];
    }
}

// ---------------------------------------------------------------------------
// K4: logits[n,c] = sum_i tanh(h_img[n,i]*h_word[c,i]) * w34[i] + b34
// ---------------------------------------------------------------------------
__global__ __launch_bounds__(128) void k_logits() {
    const int n = blockIdx.x;
    const int tid = threadIdx.x;
    const int i0 = tid * 8;
    const int lane = tid & 31;
    const int warp = tid >> 5;

    float hi[8], wv[8];
    {
        const float4* hp = (const float4*)&g_himg[(size_t)n * II + i0];
        float4 h0 = hp[0], h1 = hp[1];
        hi[0] = h0.x; hi[1] = h0.y; hi[2] = h0.z; hi[3] = h0.w;
        hi[4] = h1.x; hi[5] = h1.y; hi[6] = h1.z; hi[7] = h1.w;
        const float4* wp = (const float4*)&g_w34[i0];
        float4 w0 = wp[0], w1 = wp[1];
        wv[0] = w0.x; wv[1] = w0.y; wv[2] = w0.z; wv[3] = w0.w;
        wv[4] = w1.x; wv[5] = w1.y; wv[6] = w1.z; wv[7] = w1.w;
    }

    __shared__ float red[CC * 4];

    for (int c = 0; c < CC; c++) {
        const float4* hwp = (const float4*)&g_hword[(size_t)c * II + i0];
        float4 w0 = hwp[0], w1 = hwp[1];
        float a = 0.f;
        a += fast_tanh(hi[0] * w0.x) * wv[0];
        a += fast_tanh(hi[1] * w0.y) * wv[1];
        a += fast_tanh(hi[2] * w0.z) * wv[2];
        a += fast_tanh(hi[3] * w0.w) * wv[3];
        a += fast_tanh(hi[4] * w1.x) * wv[4];
        a += fast_tanh(hi[5] * w1.y) * wv[5];
        a += fast_tanh(hi[6] * w1.z) * wv[6];
        a += fast_tanh(hi[7] * w1.w) * wv[7];
        a += __shfl_down_sync(0xffffffff, a, 16);
        a += __shfl_down_sync(0xffffffff, a, 8);
        a += __shfl_down_sync(0xffffffff, a, 4);
        a += __shfl_down_sync(0xffffffff, a, 2);
        a += __shfl_down_sync(0xffffffff, a, 1);
        if (lane == 0) red[c * 4 + warp] = a;
    }
    __syncthreads();
    if (tid < CC) {
        float l = red[tid * 4] + red[tid * 4 + 1] + red[tid * 4 + 2] + red[tid * 4 + 3] + g_b34;
        g_logits[n * CC + tid] = l;
    }
}

// ---------------------------------------------------------------------------
// K5: softmax over 196 spatial positions per (b,c); one block per (b,c)
// ---------------------------------------------------------------------------
__global__ __launch_bounds__(256) void k_softmax(float* __restrict__ out_coef) {
    const int b = blockIdx.x / CC;
    const int c = blockIdx.x % CC;
    const int tid = threadIdx.x;
    const int lane = tid & 31;
    const int warp = tid >> 5;
    __shared__ float sm[8];

    float v = -1e30f;
    if (tid < PP) v = g_logits[((size_t)b * PP + tid) * CC + c];

    float m = v;
    m = fmaxf(m, __shfl_xor_sync(0xffffffff, m, 16));
    m = fmaxf(m, __shfl_xor_sync(0xffffffff, m, 8));
    m = fmaxf(m, __shfl_xor_sync(0xffffffff, m, 4));
    m = fmaxf(m, __shfl_xor_sync(0xffffffff, m, 2));
    m = fmaxf(m, __shfl_xor_sync(0xffffffff, m, 1));
    if (lane == 0) sm[warp] = m;
    __syncthreads();
    if (warp == 0) {
        float t = sm[lane & 7];
        t = fmaxf(t, __shfl_xor_sync(0xffffffff, t, 4));
        t = fmaxf(t, __shfl_xor_sync(0xffffffff, t, 2));
        t = fmaxf(t, __shfl_xor_sync(0xffffffff, t, 1));
        if (lane == 0) sm[0] = t;
    }
    __syncthreads();
    const float mx = sm[0];
    __syncthreads();

    float e = (tid < PP) ? expf(v - mx) : 0.f;
    float s = e;
    s += __shfl_xor_sync(0xffffffff, s, 16);
    s += __shfl_xor_sync(0xffffffff, s, 8);
    s += __shfl_xor_sync(0xffffffff, s, 4);
    s += __shfl_xor_sync(0xffffffff, s, 2);
    s += __shfl_xor_sync(0xffffffff, s, 1);
    if (lane == 0) sm[warp] = s;
    __syncthreads();
    if (warp == 0) {
        float t = sm[lane & 7];
        t += __shfl_xor_sync(0xffffffff, t, 4);
        t += __shfl_xor_sync(0xffffffff, t, 2);
        t += __shfl_xor_sync(0xffffffff, t, 1);
        if (lane == 0) sm[0] = t;
    }
    __syncthreads();
    const float inv = 1.f / sm[0];

    if (tid < PP) out_coef[((size_t)b * PP + tid) * CC + c] = e * inv;
}

// ---------------------------------------------------------------------------
// K6: fmwc[b,s1,s2,c,d] = img[b,s1,s2,d] * coef[b,s1,s2,c]
// ---------------------------------------------------------------------------
__global__ __launch_bounds__(256) void k_fmwc(const float* __restrict__ img,
                                              const float* __restrict__ coef,
                                              float* __restrict__ out_fmwc) {
    const int n = blockIdx.x;
    const int tid = threadIdx.x;
    __shared__ float4 simg[DD / 4];
    __shared__ float sc[CC];
    const float4* ip = (const float4*)&img[(size_t)n * DD];
    simg[tid] = ip[tid];
    simg[tid + 256] = ip[tid + 256];
    if (tid < CC) sc[tid] = coef[(size_t)n * CC + tid];
    __syncthreads();

    float4* op = (float4*)&out_fmwc[(size_t)n * CC * DD];
    #pragma unroll 4
    for (int idx = tid; idx < CC * (DD / 4); idx += 256) {
        int c = idx >> 9;
        int d = idx & 511;
        float4 v = simg[d];
        float s = sc[c];
        op[idx] = make_float4(v.x * s, v.y * s, v.z * s, v.w * s);
    }
}

// ---------------------------------------------------------------------------
// K7: semantic[b,c,d] = sum_p coef[b,p,c] * img[b,p,d]
// ---------------------------------------------------------------------------
__global__ __launch_bounds__(256) void k_semantic(const float* __restrict__ img,
                                                  const float* __restrict__ coef,
                                                  float* __restrict__ out_sem) {
    const int b = blockIdx.y;
    const int d = blockIdx.x * 256 + threadIdx.x;
    __shared__ float4 scoef[PP * CC / 4];
    const float4* cp = (const float4*)&coef[(size_t)b * PP * CC];
    for (int idx = threadIdx.x; idx < PP * CC / 4; idx += 256) scoef[idx] = cp[idx];
    __syncthreads();

    float acc[CC];
    #pragma unroll
    for (int c = 0; c < CC; c++) acc[c] = 0.f;

    const float* ip = &img[(size_t)b * PP * DD + d];
    #pragma unroll 2
    for (int p = 0; p < PP; p++) {
        float v = ip[(size_t)p * DD];
        #pragma unroll
        for (int c4 = 0; c4 < 5; c4++) {
            float4 cf = scoef[p * 5 + c4];
            acc[c4 * 4 + 0] += cf.x * v;
            acc[c4 * 4 + 1] += cf.y * v;
            acc[c4 * 4 + 2] += cf.z * v;
            acc[c4 * 4 + 3] += cf.w * v;
        }
    }
    #pragma unroll
    for (int c = 0; c < CC; c++)
        out_sem[((size_t)b * CC + c) * DD + d] = acc[c];
}

// ---------------------------------------------------------------------------
extern "C" void kernel_launch(void* const* d_in, const int* in_sizes, int n_in,
                              void* d_out, int out_size) {
    const float* img   = (const float*)d_in[0];  // [8,14,14,2048]
    const float* wordF = (const float*)d_in[1];  // [20,300]
    const float* W1    = (const float*)d_in[2];  // [1024,2048]
    const float* W2    = (const float*)d_in[3];  // [1024,300]
    const float* W3    = (const float*)d_in[4];  // [1024,1024]
    const float* b3    = (const float*)d_in[5];  // [1024]
    const float* W4    = (const float*)d_in[6];  // [1,1024]
    const float* b4    = (const float*)d_in[7];  // [1]

    float* out = (float*)d_out;
    float* out_sem  = out;                                      // 8*20*2048
    float* out_fmwc = out_sem + (size_t)BB * CC * DD;           // 8*14*14*20*2048
    float* out_coef = out_fmwc + (size_t)NPOS * CC * DD;        // 8*14*14*20

    // NOTE: launch order puts the GEMM 4th so the fixed `-s 5 -c 1` ncu
    // capture lands on it next round.
    k_convA<<<MPAD * DD / 4 / 256, 256>>>(img);                 // 1
    k_convB<<<II * DD / 4 / 256, 256>>>(W1);                    // 2
    k_hword<<<dim3(4, CC), 256>>>(wordF, W2);                   // 3
    k_gemm_mma<<<dim3(II / 128, MTILES), 256, GEMM_SMEM>>>();   // 4 <- profiled
    k_w34_part<<<dim3(4, 64), 256>>>(W3, W4);                   // 5
    k_w34_red<<<4, 256>>>(b3, W4, b4);                          // 6
    k_logits<<<NPOS, 128>>>();                                  // 7
    k_softmax<<<BB * CC, 256>>>(out_coef);                      // 8
    k_fmwc<<<NPOS, 256>>>(img, out_coef, out_fmwc);             // 9
    k_semantic<<<dim3(DD / 256, BB), 256>>>(img, out_coef, out_sem); // 10
}

// round 6
// speedup vs baseline: 3.1607x; 1.1993x over previous
#include <cuda_runtime.h>
#include <cuda_fp16.h>
#include <math.h>
#include <stdint.h>

// Shapes (fixed)
#define BB 8
#define SS 14
#define DD 2048
#define CC 20
#define WDIM 300
#define II 1024
#define NPOS 1568      // BB*SS*SS
#define PP 196         // SS*SS

#define MTILES 13
#define MPAD (MTILES * 128)   // 1664

// Scratch (no allocation allowed -> __device__ globals)
__device__ float g_himg[NPOS * II];     // 6.4 MB
__device__ float g_hword[CC * II];
__device__ float g_w34[II];
__device__ float g_w34p[64 * II];
__device__ float g_b34;
__device__ float g_logits[NPOS * CC];
__device__ __align__(256) __half g_Ah[(size_t)MPAD * DD];
__device__ __align__(256) __half g_Bh[(size_t)II * DD];

// ---------------------------------------------------------------------------
// PTX helpers (base PTX only)
// ---------------------------------------------------------------------------
__device__ __forceinline__ uint32_t cvta_smem(const void* p) {
    uint32_t a;
    asm("{ .reg .u64 t; cvta.to.shared.u64 t, %1; cvt.u32.u64 %0, t; }"
        : "=r"(a) : "l"(p));
    return a;
}

__device__ __forceinline__ float fast_tanh(float x) {
    float r;
    asm("tanh.approx.f32 %0, %1;" : "=f"(r) : "f"(x));
    return r;
}

__device__ __forceinline__ void cp_async16(uint32_t s, const void* g) {
    asm volatile("cp.async.cg.shared.global [%0], [%1], 16;" :: "r"(s), "l"(g));
}
#define CP_COMMIT() asm volatile("cp.async.commit_group;" ::: "memory")
#define CP_WAIT1()  asm volatile("cp.async.wait_group 1;" ::: "memory")
#define CP_WAIT0()  asm volatile("cp.async.wait_group 0;" ::: "memory")

__device__ __forceinline__ void ldsm_x4(uint32_t* r, uint32_t addr) {
    asm volatile("ldmatrix.sync.aligned.m8n8.x4.shared.b16 {%0,%1,%2,%3}, [%4];"
                 : "=r"(r[0]), "=r"(r[1]), "=r"(r[2]), "=r"(r[3]) : "r"(addr));
}

__device__ __forceinline__ void mma_fp16(float* d, const uint32_t* a, const uint32_t* b) {
    asm volatile(
        "mma.sync.aligned.m16n8k16.row.col.f32.f16.f16.f32 "
        "{%0,%1,%2,%3}, {%4,%5,%6,%7}, {%8,%9}, {%0,%1,%2,%3};"
        : "+f"(d[0]), "+f"(d[1]), "+f"(d[2]), "+f"(d[3])
        : "r"(a[0]), "r"(a[1]), "r"(a[2]), "r"(a[3]), "r"(b[0]), "r"(b[1]));
}

// ---------------------------------------------------------------------------
// Conversion kernel: fp32 -> fp16 for both A (img, padded) and B (W1)
// ---------------------------------------------------------------------------
#define CONV_A_BLOCKS (MPAD * DD / 4 / 256)   // 3328
#define CONV_B_BLOCKS (II * DD / 4 / 256)     // 2048

__global__ __launch_bounds__(256) void k_conv(const float* __restrict__ img,
                                              const float* __restrict__ W1) {
    int blk = blockIdx.x;
    if (blk < CONV_A_BLOCKS) {
        size_t t = (size_t)blk * 256 + threadIdx.x;
        size_t base = t * 4;
        size_t row = base / DD;
        float4 v = make_float4(0.f, 0.f, 0.f, 0.f);
        if (row < NPOS) v = *(const float4*)&img[base];
        __half2 h0 = __floats2half2_rn(v.x, v.y);
        __half2 h1 = __floats2half2_rn(v.z, v.w);
        uint2 o;
        o.x = *reinterpret_cast<uint32_t*>(&h0);
        o.y = *reinterpret_cast<uint32_t*>(&h1);
        *(uint2*)&g_Ah[base] = o;
    } else {
        size_t t = (size_t)(blk - CONV_A_BLOCKS) * 256 + threadIdx.x;
        size_t base = t * 4;
        float4 v = *(const float4*)&W1[base];
        __half2 h0 = __floats2half2_rn(v.x, v.y);
        __half2 h1 = __floats2half2_rn(v.z, v.w);
        uint2 o;
        o.x = *reinterpret_cast<uint32_t*>(&h0);
        o.y = *reinterpret_cast<uint32_t*>(&h1);
        *(uint2*)&g_Bh[base] = o;
    }
}

// ---------------------------------------------------------------------------
// mma.sync fp16 GEMM: h_img[1568(pad1664), 1024] = A[M,2048] @ W1[1024,2048]^T
// BM=128, BN=64, BK=32, 3-stage cp.async, grid (16,13)=208 CTAs.
// Rows padded to 80B in smem -> conflict-free ldmatrix without XOR swizzle.
// ---------------------------------------------------------------------------
#define BK 32
#define ROWB 80                       // 64B data + 16B pad per k-row of 32 fp16
#define A_TILE_B (128 * ROWB)         // 10240
#define B_TILE_B (64 * ROWB)          // 5120
#define STAGE_BYTES (A_TILE_B + B_TILE_B)   // 15360
#define NSTAGE 3
#define GEMM_SMEM (NSTAGE * STAGE_BYTES)    // 46080 < 48K
#define NK (DD / BK)                  // 64

#define A_OFF 0
#define B_OFF A_TILE_B

__global__ __launch_bounds__(256) void k_gemm_mma() {
    extern __shared__ __align__(16) char dsm[];
    const uint32_t smem = cvta_smem(dsm);

    const int tid = threadIdx.x;
    const int wid = tid >> 5;
    const int lane = tid & 31;
    const int bm = blockIdx.y * 128;
    const int bn = blockIdx.x * 64;
    const int wm = (wid & 3) * 32;       // warp rows [wm, wm+32)
    const int wn = (wid >> 2) * 32;      // warp cols [wn, wn+32)

    // global->smem mapping: 768 16B chunks per stage, 3 per thread
    // j0: A rows 0-63, j1: A rows 64-127, j2: B rows 0-63
    const int grow = tid >> 2;           // 0..63
    const int gch = tid & 3;             // 0..3
    const __half* pA0 = &g_Ah[(size_t)(bm + grow) * DD + gch * 8];
    const __half* pA1 = &g_Ah[(size_t)(bm + 64 + grow) * DD + gch * 8];
    const __half* pB  = &g_Bh[(size_t)(bn + grow) * DD + gch * 8];
    const uint32_t sA0 = (uint32_t)(grow * ROWB + gch * 16);
    const uint32_t sA1 = (uint32_t)((64 + grow) * ROWB + gch * 16);
    const uint32_t sB  = (uint32_t)(grow * ROWB + gch * 16);

    // ldmatrix offsets
    // A m16k16 frag: lanes 0-15 -> rows, lanes 16-31 -> +16B chunk
    uint32_t aoff[2][2];  // [m][ksub]
    uint32_t boff[2][2];  // [npair][ksub], each x4 = 16 cols x 16 k
    {
        int r = lane & 15, c = lane >> 4;
        #pragma unroll
        for (int m = 0; m < 2; m++)
            #pragma unroll
            for (int ks = 0; ks < 2; ks++)
                aoff[m][ks] = (uint32_t)((wm + m * 16 + r) * ROWB + ks * 32 + c * 16);
        int br = ((lane >> 4) * 8) + (lane & 7);
        int bc = (lane >> 3) & 1;
        #pragma unroll
        for (int np = 0; np < 2; np++)
            #pragma unroll
            for (int ks = 0; ks < 2; ks++)
                boff[np][ks] = (uint32_t)((wn + np * 16 + br) * ROWB + ks * 32 + bc * 16);
    }

    float acc[2][4][4];   // [m][nblk of 8][4]
    #pragma unroll
    for (int i = 0; i < 2; i++)
        #pragma unroll
        for (int j = 0; j < 4; j++)
            #pragma unroll
            for (int q = 0; q < 4; q++) acc[i][j][q] = 0.f;

    auto load_stage = [&](int kc, int buf) {
        uint32_t sb = smem + buf * STAGE_BYTES;
        size_t go = (size_t)kc * BK;
        cp_async16(sb + A_OFF + sA0, pA0 + go);
        cp_async16(sb + A_OFF + sA1, pA1 + go);
        cp_async16(sb + B_OFF + sB,  pB  + go);
    };

    load_stage(0, 0); CP_COMMIT();
    load_stage(1, 1); CP_COMMIT();

    int buf = 0;
    for (int it = 0; it < NK; it++) {
        if (it + 1 < NK) { CP_WAIT1(); } else { CP_WAIT0(); }
        __syncthreads();
        if (it + 2 < NK) { load_stage(it + 2, (buf + 2) % NSTAGE); CP_COMMIT(); }

        uint32_t sb = smem + buf * STAGE_BYTES;
        uint32_t af[2][2][4];         // [ksub][m][4]
        uint32_t bfr[2][4][2];        // [ksub][nblk][2]
        #pragma unroll
        for (int ks = 0; ks < 2; ks++) {
            #pragma unroll
            for (int m = 0; m < 2; m++)
                ldsm_x4(af[ks][m], sb + A_OFF + aoff[m][ks]);
            #pragma unroll
            for (int np = 0; np < 2; np++) {
                uint32_t t4[4];
                ldsm_x4(t4, sb + B_OFF + boff[np][ks]);
                bfr[ks][2 * np][0] = t4[0]; bfr[ks][2 * np][1] = t4[1];
                bfr[ks][2 * np + 1][0] = t4[2]; bfr[ks][2 * np + 1][1] = t4[3];
            }
        }
        #pragma unroll
        for (int ks = 0; ks < 2; ks++)
            #pragma unroll
            for (int m = 0; m < 2; m++)
                #pragma unroll
                for (int n = 0; n < 4; n++)
                    mma_fp16(acc[m][n], af[ks][m], bfr[ks][n]);
        buf = (buf + 1) % NSTAGE;
    }

    // epilogue
    const int er = lane >> 2;
    const int ec = (lane & 3) * 2;
    #pragma unroll
    for (int m = 0; m < 2; m++) {
        int row0 = bm + wm + m * 16 + er;
        #pragma unroll
        for (int n = 0; n < 4; n++) {
            int col = bn + wn + n * 8 + ec;
            if (row0 < NPOS)
                *(float2*)&g_himg[(size_t)row0 * II + col] = make_float2(acc[m][n][0], acc[m][n][1]);
            if (row0 + 8 < NPOS)
                *(float2*)&g_himg[(size_t)(row0 + 8) * II + col] = make_float2(acc[m][n][2], acc[m][n][3]);
        }
    }
}

// ---------------------------------------------------------------------------
// K1: h_word[c,i] = sum_d wordF[c,d] * W2[i,d]   grid (4, CC)
// ---------------------------------------------------------------------------
__global__ __launch_bounds__(256) void k_hword(const float* __restrict__ wordF,
                                               const float* __restrict__ W2) {
    const int c = blockIdx.y;
    const int i = blockIdx.x * 256 + threadIdx.x;
    __shared__ float sw[WDIM + 4];
    for (int d = threadIdx.x; d < WDIM; d += 256) sw[d] = wordF[c * WDIM + d];
    if (threadIdx.x < 4) sw[WDIM + threadIdx.x] = 0.f;
    __syncthreads();
    const float* w2r = &W2[(size_t)i * WDIM];
    float a0 = 0.f, a1 = 0.f, a2 = 0.f, a3 = 0.f;
    #pragma unroll 5
    for (int d = 0; d < WDIM; d += 4) {
        a0 += sw[d + 0] * w2r[d + 0];
        a1 += sw[d + 1] * w2r[d + 1];
        a2 += sw[d + 2] * w2r[d + 2];
        a3 += sw[d + 3] * w2r[d + 3];
    }
    g_hword[c * II + i] = (a0 + a1) + (a2 + a3);
}

// ---------------------------------------------------------------------------
// K2a: partial w34. grid (4 i-chunks, 64 j-chunks); one i per thread.
// ---------------------------------------------------------------------------
__global__ __launch_bounds__(256) void k_w34_part(const float* __restrict__ W3,
                                                  const float* __restrict__ W4) {
    const int i = blockIdx.x * 256 + threadIdx.x;   // 0..1023
    const int jb = blockIdx.y;                      // 0..63
    const int j0 = jb * 16;
    float acc = 0.f;
    #pragma unroll
    for (int j = 0; j < 16; j++)
        acc += W4[j0 + j] * W3[(size_t)(j0 + j) * II + i];
    g_w34p[(size_t)jb * II + i] = acc;
}

// K2b: reduce partials + b34
__global__ __launch_bounds__(256) void k_w34_red(const float* __restrict__ b3,
                                                 const float* __restrict__ W4,
                                                 const float* __restrict__ b4) {
    const int i = blockIdx.x * 256 + threadIdx.x;
    float s = 0.f;
    #pragma unroll 8
    for (int k = 0; k < 64; k++) s += g_w34p[(size_t)k * II + i];
    g_w34[i] = s;

    if (blockIdx.x == 0) {
        __shared__ float sred[256];
        float a = 0.f;
        for (int j = threadIdx.x; j < II; j += 256) a += W4[j] * b3[j];
        sred[threadIdx.x] = a;
        __syncthreads();
        for (int st = 128; st > 0; st >>= 1) {
            if (threadIdx.x < st) sred[threadIdx.x] += sred[threadIdx.x + st];
            __syncthreads();
        }
        if (threadIdx.x == 0) g_b34 = sred[0] + b4[0];
    }
}

// ---------------------------------------------------------------------------
// K4: logits[n,c] = sum_i tanh(h_img[n,i]*h_word[c,i]) * w34[i] + b34
// ---------------------------------------------------------------------------
__global__ __launch_bounds__(128) void k_logits() {
    const int n = blockIdx.x;
    const int tid = threadIdx.x;
    const int i0 = tid * 8;
    const int lane = tid & 31;
    const int warp = tid >> 5;

    float hi[8], wv[8];
    {
        const float4* hp = (const float4*)&g_himg[(size_t)n * II + i0];
        float4 h0 = hp[0], h1 = hp[1];
        hi[0] = h0.x; hi[1] = h0.y; hi[2] = h0.z; hi[3] = h0.w;
        hi[4] = h1.x; hi[5] = h1.y; hi[6] = h1.z; hi[7] = h1.w;
        const float4* wp = (const float4*)&g_w34[i0];
        float4 w0 = wp[0], w1 = wp[1];
        wv[0] = w0.x; wv[1] = w0.y; wv[2] = w0.z; wv[3] = w0.w;
        wv[4] = w1.x; wv[5] = w1.y; wv[6] = w1.z; wv[7] = w1.w;
    }

    __shared__ float red[CC * 4];

    for (int c = 0; c < CC; c++) {
        const float4* hwp = (const float4*)&g_hword[(size_t)c * II + i0];
        float4 w0 = hwp[0], w1 = hwp[1];
        float a = 0.f;
        a += fast_tanh(hi[0] * w0.x) * wv[0];
        a += fast_tanh(hi[1] * w0.y) * wv[1];
        a += fast_tanh(hi[2] * w0.z) * wv[2];
        a += fast_tanh(hi[3] * w0.w) * wv[3];
        a += fast_tanh(hi[4] * w1.x) * wv[4];
        a += fast_tanh(hi[5] * w1.y) * wv[5];
        a += fast_tanh(hi[6] * w1.z) * wv[6];
        a += fast_tanh(hi[7] * w1.w) * wv[7];
        a += __shfl_down_sync(0xffffffff, a, 16);
        a += __shfl_down_sync(0xffffffff, a, 8);
        a += __shfl_down_sync(0xffffffff, a, 4);
        a += __shfl_down_sync(0xffffffff, a, 2);
        a += __shfl_down_sync(0xffffffff, a, 1);
        if (lane == 0) red[c * 4 + warp] = a;
    }
    __syncthreads();
    if (tid < CC) {
        float l = red[tid * 4] + red[tid * 4 + 1] + red[tid * 4 + 2] + red[tid * 4 + 3] + g_b34;
        g_logits[n * CC + tid] = l;
    }
}

// ---------------------------------------------------------------------------
// K5: softmax over 196 spatial positions per (b,c); one block per (b,c)
// ---------------------------------------------------------------------------
__global__ __launch_bounds__(256) void k_softmax(float* __restrict__ out_coef) {
    const int b = blockIdx.x / CC;
    const int c = blockIdx.x % CC;
    const int tid = threadIdx.x;
    const int lane = tid & 31;
    const int warp = tid >> 5;
    __shared__ float sm[8];

    float v = -1e30f;
    if (tid < PP) v = g_logits[((size_t)b * PP + tid) * CC + c];

    float m = v;
    m = fmaxf(m, __shfl_xor_sync(0xffffffff, m, 16));
    m = fmaxf(m, __shfl_xor_sync(0xffffffff, m, 8));
    m = fmaxf(m, __shfl_xor_sync(0xffffffff, m, 4));
    m = fmaxf(m, __shfl_xor_sync(0xffffffff, m, 2));
    m = fmaxf(m, __shfl_xor_sync(0xffffffff, m, 1));
    if (lane == 0) sm[warp] = m;
    __syncthreads();
    if (warp == 0) {
        float t = sm[lane & 7];
        t = fmaxf(t, __shfl_xor_sync(0xffffffff, t, 4));
        t = fmaxf(t, __shfl_xor_sync(0xffffffff, t, 2));
        t = fmaxf(t, __shfl_xor_sync(0xffffffff, t, 1));
        if (lane == 0) sm[0] = t;
    }
    __syncthreads();
    const float mx = sm[0];
    __syncthreads();

    float e = (tid < PP) ? expf(v - mx) : 0.f;
    float s = e;
    s += __shfl_xor_sync(0xffffffff, s, 16);
    s += __shfl_xor_sync(0xffffffff, s, 8);
    s += __shfl_xor_sync(0xffffffff, s, 4);
    s += __shfl_xor_sync(0xffffffff, s, 2);
    s += __shfl_xor_sync(0xffffffff, s, 1);
    if (lane == 0) sm[warp] = s;
    __syncthreads();
    if (warp == 0) {
        float t = sm[lane & 7];
        t += __shfl_xor_sync(0xffffffff, t, 4);
        t += __shfl_xor_sync(0xffffffff, t, 2);
        t += __shfl_xor_sync(0xffffffff, t, 1);
        if (lane == 0) sm[0] = t;
    }
    __syncthreads();
    const float inv = 1.f / sm[0];

    if (tid < PP) out_coef[((size_t)b * PP + tid) * CC + c] = e * inv;
}

// ---------------------------------------------------------------------------
// K6: fmwc[b,s1,s2,c,d] = img[b,s1,s2,d] * coef[b,s1,s2,c]  (streaming stores)
// ---------------------------------------------------------------------------
__global__ __launch_bounds__(256) void k_fmwc(const float* __restrict__ img,
                                              const float* __restrict__ coef,
                                              float* __restrict__ out_fmwc) {
    const int n = blockIdx.x;
    const int tid = threadIdx.x;
    __shared__ float4 simg[DD / 4];
    __shared__ float sc[CC];
    const float4* ip = (const float4*)&img[(size_t)n * DD];
    simg[tid] = ip[tid];
    simg[tid + 256] = ip[tid + 256];
    if (tid < CC) sc[tid] = coef[(size_t)n * CC + tid];
    __syncthreads();

    float4* op = (float4*)&out_fmwc[(size_t)n * CC * DD];
    #pragma unroll 4
    for (int idx = tid; idx < CC * (DD / 4); idx += 256) {
        int c = idx >> 9;
        int d = idx & 511;
        float4 v = simg[d];
        float s = sc[c];
        __stcs(&op[idx], make_float4(v.x * s, v.y * s, v.z * s, v.w * s));
    }
}

// ---------------------------------------------------------------------------
// K7: semantic[b,c,d] = sum_p coef[b,p,c] * img[b,p,d]
// ---------------------------------------------------------------------------
__global__ __launch_bounds__(256) void k_semantic(const float* __restrict__ img,
                                                  const float* __restrict__ coef,
                                                  float* __restrict__ out_sem) {
    const int b = blockIdx.y;
    const int d = blockIdx.x * 256 + threadIdx.x;
    __shared__ float4 scoef[PP * CC / 4];
    const float4* cp = (const float4*)&coef[(size_t)b * PP * CC];
    for (int idx = threadIdx.x; idx < PP * CC / 4; idx += 256) scoef[idx] = cp[idx];
    __syncthreads();

    float acc[CC];
    #pragma unroll
    for (int c = 0; c < CC; c++) acc[c] = 0.f;

    const float* ip = &img[(size_t)b * PP * DD + d];
    #pragma unroll 2
    for (int p = 0; p < PP; p++) {
        float v = ip[(size_t)p * DD];
        #pragma unroll
        for (int c4 = 0; c4 < 5; c4++) {
            float4 cf = scoef[p * 5 + c4];
            acc[c4 * 4 + 0] += cf.x * v;
            acc[c4 * 4 + 1] += cf.y * v;
            acc[c4 * 4 + 2] += cf.z * v;
            acc[c4 * 4 + 3] += cf.w * v;
        }
    }
    #pragma unroll
    for (int c = 0; c < CC; c++)
        out_sem[((size_t)b * CC + c) * DD + d] = acc[c];
}

// ---------------------------------------------------------------------------
extern "C" void kernel_launch(void* const* d_in, const int* in_sizes, int n_in,
                              void* d_out, int out_size) {
    const float* img   = (const float*)d_in[0];  // [8,14,14,2048]
    const float* wordF = (const float*)d_in[1];  // [20,300]
    const float* W1    = (const float*)d_in[2];  // [1024,2048]
    const float* W2    = (const float*)d_in[3];  // [1024,300]
    const float* W3    = (const float*)d_in[4];  // [1024,1024]
    const float* b3    = (const float*)d_in[5];  // [1024]
    const float* W4    = (const float*)d_in[6];  // [1,1024]
    const float* b4    = (const float*)d_in[7];  // [1]

    float* out = (float*)d_out;
    float* out_sem  = out;                                      // 8*20*2048
    float* out_fmwc = out_sem + (size_t)BB * CC * DD;           // 8*14*14*20*2048
    float* out_coef = out_fmwc + (size_t)NPOS * CC * DD;        // 8*14*14*20

    // GEMM kept as the 4th launch for the fixed ncu capture slot.
    k_conv<<<CONV_A_BLOCKS + CONV_B_BLOCKS, 256>>>(img, W1);    // 1
    k_hword<<<dim3(4, CC), 256>>>(wordF, W2);                   // 2
    k_w34_part<<<dim3(4, 64), 256>>>(W3, W4);                   // 3
    k_gemm_mma<<<dim3(II / 64, MTILES), 256, GEMM_SMEM>>>();    // 4 <- profiled
    k_w34_red<<<4, 256>>>(b3, W4, b4);                          // 5
    k_logits<<<NPOS, 128>>>();                                  // 6
    k_softmax<<<BB * CC, 256>>>(out_coef);                      // 7
    k_fmwc<<<NPOS, 256>>>(img, out_coef, out_fmwc);             // 8
    k_semantic<<<dim3(DD / 256, BB), 256>>>(img, out_coef, out_sem); // 9
}